// round 1
// baseline (speedup 1.0000x reference)
#include <cuda_runtime.h>
#include <cuda_bf16.h>

// ---------------- problem constants ----------------
#define N_SPANS   2000
#define D_SPAN    1220
#define NPAIRS    65536
#define HID       150
#define HPAD      160          // padded hidden dim (zero-padded 150..159)
#define NPHI      189          // 9 bins * 7 genres * 3 speakers

// ---------------- scratch (static device memory; no allocs) ----------------
__device__ __align__(256) float d_Cpart[8][N_SPANS * HPAD];  // GEMM k-split partials
__device__ __align__(256) float d_TA[N_SPANS * HPAD];        // g[m] @ W1a
__device__ __align__(256) float d_TB[N_SPANS * HPAD];        // g[a] @ W1b + g[a]^2 @ W1c
__device__ __align__(256) float d_TPHI[NPHI * HPAD];         // phi @ W1d + b1

// =====================================================================
// K_phi: TPHI[c][j] = b1[j] + sum_t dist/genre/spk embeddings @ W1[3660..3719]
// grid=189 blocks, 160 threads
// =====================================================================
__global__ void k_phi(const float* __restrict__ de, const float* __restrict__ ge,
                      const float* __restrict__ se, const float* __restrict__ W1,
                      const float* __restrict__ b1)
{
    int c = blockIdx.x;
    int j = threadIdx.x;
    int bin = c / 21;
    int r   = c % 21;
    int gg  = r / 3;
    int ss  = r % 3;
    float v = 0.0f;
    if (j < HID) {
        v = b1[j];
        #pragma unroll
        for (int t = 0; t < 20; ++t) {
            v += de[bin * 20 + t] * W1[(3660 + t) * HID + j];
            v += ge[gg  * 20 + t] * W1[(3680 + t) * HID + j];
            v += se[ss  * 20 + t] * W1[(3700 + t) * HID + j];
        }
    }
    d_TPHI[c * HPAD + j] = v;
}

// =====================================================================
// K1: precompute TA / TB partials.
//   grid = (63 mtiles, 8 slots).  slot 0..2 -> TA k-chunks (K=1220)
//   slot 3..7 -> TB k-chunks over virtual K=2440:
//      A'(m,k) = k<1220 ? g[m][k] : g[m][k-1220]^2 ;  B'(k,j) = W1[1220+k][j]
//   80 threads, thread tile 8j x 8m, BM=32, BN=160 (j zero-padded >=150)
// =====================================================================
__global__ __launch_bounds__(80) void k_precompute(const float* __restrict__ g,
                                                   const float* __restrict__ W1)
{
    __shared__ __align__(16) float Asm[16][36];     // [k][m], padded stride 36
    __shared__ __align__(16) float Bsm[16][164];    // [k][j], padded stride 164

    const int mtile = blockIdx.x;     // 0..62
    const int slot  = blockIdx.y;     // 0..7
    const int mbase = mtile * 32;

    int kbase, klen, wrow0;
    bool zb;
    if (slot < 3) { kbase = slot * 407; klen = (slot == 2) ? 406 : 407; wrow0 = 0;    zb = false; }
    else          { kbase = (slot - 3) * 488; klen = 488;               wrow0 = 1220; zb = true;  }

    const int tid = threadIdx.x;
    const int jt  = tid % 20;
    const int mt  = tid / 20;
    const int j0  = jt * 8;
    const int m0  = mt * 8;

    float acc[8][8];
    #pragma unroll
    for (int a = 0; a < 8; ++a)
        #pragma unroll
        for (int b = 0; b < 8; ++b) acc[a][b] = 0.0f;

    for (int kc = 0; kc < klen; kc += 16) {
        // ---- stage B' chunk: 16 rows x 160 cols (float2 per thread per row) ----
        {
            int q = tid;              // 0..79 -> j = 2q covers 0..158
            int j = q * 2;
            #pragma unroll 4
            for (int row = 0; row < 16; ++row) {
                float2 v = make_float2(0.0f, 0.0f);
                if ((kc + row) < klen && j < HID) {
                    int wrow = wrow0 + kbase + kc + row;
                    v = *(const float2*)(W1 + wrow * HID + j);
                }
                Bsm[row][j]     = v.x;
                Bsm[row][j + 1] = v.y;
            }
        }
        // ---- stage A' chunk: 32 m x 16 k (transposed into Asm[k][m]) ----
        for (int i = tid; i < 512; i += 80) {
            int m  = i / 16;
            int kq = i % 16;
            float v = 0.0f;
            if ((mbase + m) < N_SPANS && (kc + kq) < klen) {
                int gk = kbase + kc + kq;
                if (zb && gk >= D_SPAN) {
                    float t = g[(mbase + m) * D_SPAN + (gk - D_SPAN)];
                    v = t * t;
                } else {
                    v = g[(mbase + m) * D_SPAN + gk];
                }
            }
            Asm[kq][m] = v;
        }
        __syncthreads();

        // ---- 8x8 register-tile FMA over 16 k ----
        #pragma unroll
        for (int kk = 0; kk < 16; ++kk) {
            float4 a0 = *(const float4*)&Asm[kk][m0];
            float4 a1 = *(const float4*)&Asm[kk][m0 + 4];
            float4 b0 = *(const float4*)&Bsm[kk][j0];
            float4 b1 = *(const float4*)&Bsm[kk][j0 + 4];
            float av[8] = {a0.x, a0.y, a0.z, a0.w, a1.x, a1.y, a1.z, a1.w};
            float bv[8] = {b0.x, b0.y, b0.z, b0.w, b1.x, b1.y, b1.z, b1.w};
            #pragma unroll
            for (int mm = 0; mm < 8; ++mm)
                #pragma unroll
                for (int jj = 0; jj < 8; ++jj)
                    acc[mm][jj] += av[mm] * bv[jj];
        }
        __syncthreads();
    }

    // ---- write partials ----
    #pragma unroll
    for (int mm = 0; mm < 8; ++mm) {
        int m = mbase + m0 + mm;
        if (m < N_SPANS) {
            #pragma unroll
            for (int jj = 0; jj < 8; ++jj)
                d_Cpart[slot][m * HPAD + j0 + jj] = acc[mm][jj];
        }
    }
}

// =====================================================================
// K2: reduce k-split partials into TA / TB
// =====================================================================
__global__ void k_reduce()
{
    int idx = blockIdx.x * blockDim.x + threadIdx.x;
    if (idx < N_SPANS * HPAD) {
        d_TA[idx] = d_Cpart[0][idx] + d_Cpart[1][idx] + d_Cpart[2][idx];
        d_TB[idx] = d_Cpart[3][idx] + d_Cpart[4][idx] + d_Cpart[5][idx]
                  + d_Cpart[6][idx] + d_Cpart[7][idx];
    }
}

// =====================================================================
// K3: fused pair kernel.
//   512 blocks x 320 threads; 128 pairs / block.
//   stage1: h1 = relu(TA[m]+TB[a]+TPHI[c])  -> H1 smem, transposed [k][p]
//   stage2: h2 = relu(h1 @ W2 + b2); s = h2 . W3; out = s + b3 + s_m[m] + s_m[a]
//   thread tile: 8 contiguous j (jt=tid/16, 20 groups) x 8 strided p (pt=tid%16)
// =====================================================================
#define H1_STRIDE 129
#define OFF_H1 0                                  // 160*129 = 20640 floats
#define OFF_W2 20640                              // 32*160 = 5120 (union w/ red)
#define OFF_W3 25760                              // 160
#define OFF_B2 25920                              // 160
#define OFF_SB 26080                              // 128
#define OFF_M  26208                              // 128 ints
#define OFF_A  26336                              // 128 ints
#define OFF_C  26464                              // 128 ints
#define SMEM_FLOATS 26592
#define SMEM_BYTES (SMEM_FLOATS * 4)

__global__ __launch_bounds__(320, 2) void k_pairs(
    const float* __restrict__ s_m, const int* __restrict__ mids,
    const int* __restrict__ aids, const int* __restrict__ dist,
    const int* __restrict__ genre, const int* __restrict__ spk,
    const float* __restrict__ W2, const float* __restrict__ b2,
    const float* __restrict__ W3, const float* __restrict__ b3,
    float* __restrict__ out)
{
    extern __shared__ float S[];
    float* H1  = S + OFF_H1;
    float* W2s = S + OFF_W2;
    float* red = S + OFF_W2;   // reused after GEMM
    float* W3s = S + OFF_W3;
    float* b2s = S + OFF_B2;
    float* sb  = S + OFF_SB;
    int*   mS  = (int*)(S + OFF_M);
    int*   aS  = (int*)(S + OFF_A);
    int*   cS  = (int*)(S + OFF_C);

    const int tid   = threadIdx.x;
    const int pbase = blockIdx.x * 128;

    // ---- per-pair metadata ----
    if (tid < 128) {
        int p = pbase + tid;
        int m = mids[p];
        int a = aids[p];
        mS[tid] = m;
        aS[tid] = a;
        int d = dist[p];
        int bin;
        if      (d >= 64) bin = 8;
        else if (d >= 32) bin = 7;
        else if (d >= 16) bin = 6;
        else if (d >= 8)  bin = 5;
        else if (d >= 5)  bin = 4;
        else              bin = (d >= 1) ? (d - 1) : 0;
        cS[tid] = (bin * 7 + genre[p]) * 3 + spk[p];
        sb[tid] = s_m[m] + s_m[a];
    }
    if (tid < HPAD) {
        float w3v = 0.0f, b2v = 0.0f;
        if (tid < HID) { w3v = W3[tid]; b2v = b2[tid]; }
        W3s[tid] = w3v;
        b2s[tid] = b2v;
    }
    __syncthreads();

    // ---- stage 1: gather + add + relu -> H1[k][p] (transposed) ----
    {
        const float4* TA4 = (const float4*)d_TA;
        const float4* TB4 = (const float4*)d_TB;
        const float4* TP4 = (const float4*)d_TPHI;
        for (int i = tid; i < 128 * 40; i += 320) {
            int p = i / 40;
            int q = i % 40;
            float4 va = TA4[mS[p] * 40 + q];
            float4 vb = TB4[aS[p] * 40 + q];
            float4 vc = TP4[cS[p] * 40 + q];
            float hx = fmaxf(va.x + vb.x + vc.x, 0.0f);
            float hy = fmaxf(va.y + vb.y + vc.y, 0.0f);
            float hz = fmaxf(va.z + vb.z + vc.z, 0.0f);
            float hw = fmaxf(va.w + vb.w + vc.w, 0.0f);
            int k = q * 4;
            H1[(k + 0) * H1_STRIDE + p] = hx;
            H1[(k + 1) * H1_STRIDE + p] = hy;
            H1[(k + 2) * H1_STRIDE + p] = hz;
            H1[(k + 3) * H1_STRIDE + p] = hw;
        }
    }
    __syncthreads();

    // ---- stage 2: GEMM h2pre[p][j] = sum_k H1[k][p] * W2[k][j] ----
    const int pt = tid % 16;
    const int jt = tid / 16;          // 0..19
    const int j0 = jt * 8;

    float acc[8][8];                  // [s (p-strided)][jj]
    #pragma unroll
    for (int s = 0; s < 8; ++s)
        #pragma unroll
        for (int jj = 0; jj < 8; ++jj) acc[s][jj] = 0.0f;

    for (int kc = 0; kc < HPAD; kc += 32) {
        // stage W2 chunk: rows kc..kc+31, zero-padded
        #pragma unroll
        for (int r = 0; r < 8; ++r) {
            int i   = r * 320 + tid;       // 0..2559
            int row = i / 80;
            int q   = i % 80;
            int j   = q * 2;
            float2 v = make_float2(0.0f, 0.0f);
            int gr = kc + row;
            if (gr < HID && j < HID)
                v = *(const float2*)(W2 + gr * HID + j);
            W2s[row * HPAD + j]     = v.x;
            W2s[row * HPAD + j + 1] = v.y;
        }
        __syncthreads();

        #pragma unroll 4
        for (int kk = 0; kk < 32; ++kk) {
            int k = kc + kk;
            float4 b0 = *(const float4*)&W2s[kk * HPAD + j0];
            float4 b1 = *(const float4*)&W2s[kk * HPAD + j0 + 4];
            float bv[8] = {b0.x, b0.y, b0.z, b0.w, b1.x, b1.y, b1.z, b1.w};
            float av[8];
            #pragma unroll
            for (int s = 0; s < 8; ++s)
                av[s] = H1[k * H1_STRIDE + pt + 16 * s];
            #pragma unroll
            for (int s = 0; s < 8; ++s)
                #pragma unroll
                for (int jj = 0; jj < 8; ++jj)
                    acc[s][jj] += av[s] * bv[jj];
        }
        __syncthreads();
    }

    // ---- epilogue: relu + dot W3, partial per (jt, p) ----
    float sp[8];
    #pragma unroll
    for (int s = 0; s < 8; ++s) sp[s] = 0.0f;
    #pragma unroll
    for (int jj = 0; jj < 8; ++jj) {
        float w3 = W3s[j0 + jj];
        float bb = b2s[j0 + jj];
        #pragma unroll
        for (int s = 0; s < 8; ++s) {
            float h2 = fmaxf(acc[s][jj] + bb, 0.0f);
            sp[s] += h2 * w3;
        }
    }
    #pragma unroll
    for (int s = 0; s < 8; ++s)
        red[jt * 128 + pt + 16 * s] = sp[s];
    __syncthreads();

    if (tid < 128) {
        float t = 0.0f;
        #pragma unroll
        for (int r = 0; r < 20; ++r) t += red[r * 128 + tid];
        out[pbase + tid] = t + b3[0] + sb[tid];
    }
}

// =====================================================================
// launch
// =====================================================================
extern "C" void kernel_launch(void* const* d_in, const int* in_sizes, int n_in,
                              void* d_out, int out_size)
{
    const float* g    = (const float*)d_in[0];
    const float* s_m  = (const float*)d_in[1];
    const int*   mids = (const int*)d_in[2];
    const int*   aids = (const int*)d_in[3];
    const int*   dist = (const int*)d_in[4];
    const int*   genr = (const int*)d_in[5];
    const int*   spk  = (const int*)d_in[6];
    const float* de   = (const float*)d_in[7];
    const float* ge   = (const float*)d_in[8];
    const float* se   = (const float*)d_in[9];
    const float* W1   = (const float*)d_in[10];
    const float* b1   = (const float*)d_in[11];
    const float* W2   = (const float*)d_in[12];
    const float* b2   = (const float*)d_in[13];
    const float* W3   = (const float*)d_in[14];
    const float* b3   = (const float*)d_in[15];
    float* out = (float*)d_out;

    cudaFuncSetAttribute(k_pairs, cudaFuncAttributeMaxDynamicSharedMemorySize, SMEM_BYTES);

    k_phi<<<NPHI, HPAD>>>(de, ge, se, W1, b1);
    k_precompute<<<dim3(63, 8), 80>>>(g, W1);
    k_reduce<<<(N_SPANS * HPAD + 255) / 256, 256>>>();
    k_pairs<<<NPAIRS / 128, 320, SMEM_BYTES>>>(s_m, mids, aids, dist, genr, spk,
                                               W2, b2, W3, b3, out);
}

// round 3
// speedup vs baseline: 1.3041x; 1.3041x over previous
#include <cuda_runtime.h>
#include <cuda_bf16.h>

// ---------------- problem constants ----------------
#define N_SPANS   2000
#define D_SPAN    1220
#define NPAIRS    65536
#define HID       150
#define HPAD      160          // padded hidden dim (zero-padded 150..159)
#define NPHI      189          // 9 bins * 7 genres * 3 speakers
#define NSLOTS    18           // 6 TA k-chunks + 12 TB k-chunks

// ---------------- scratch (static device memory; no allocs) ----------------
__device__ __align__(256) float d_Cpart[NSLOTS][N_SPANS * HPAD];
__device__ __align__(256) float d_TA[N_SPANS * HPAD];        // g[m] @ W1a
__device__ __align__(256) float d_TB[N_SPANS * HPAD];        // g[a] @ W1b + g[a]^2 @ W1c
__device__ __align__(256) float d_TPHI[NPHI * HPAD];         // phi @ W1d + b1

__device__ __forceinline__ unsigned f2tf32(float x) {
    unsigned r;
    asm("cvt.rna.tf32.f32 %0, %1;" : "=r"(r) : "f"(x));
    return r;
}

// =====================================================================
// K_phi: TPHI[c][j] = b1[j] + phi-embedding combo c @ W1[3660..3719]
// =====================================================================
__global__ void k_phi(const float* __restrict__ de, const float* __restrict__ ge,
                      const float* __restrict__ se, const float* __restrict__ W1,
                      const float* __restrict__ b1)
{
    int c = blockIdx.x;
    int j = threadIdx.x;
    int bin = c / 21;
    int r   = c % 21;
    int gg  = r / 3;
    int ss  = r % 3;
    float v = 0.0f;
    if (j < HID) {
        v = b1[j];
        #pragma unroll
        for (int t = 0; t < 20; ++t) {
            v += de[bin * 20 + t] * W1[(3660 + t) * HID + j];
            v += ge[gg  * 20 + t] * W1[(3680 + t) * HID + j];
            v += se[ss  * 20 + t] * W1[(3700 + t) * HID + j];
        }
    }
    d_TPHI[c * HPAD + j] = v;
}

// =====================================================================
// K1: precompute TA / TB partials.
//   grid = (16 mtiles, 18 slots), 320 threads, BM=128, BN=160.
//   slots 0..5  -> TA k-chunks of 204 over K=1220
//   slots 6..17 -> TB k-chunks of 204 over virtual K=2440:
//      A'(m,k) = k<1220 ? g[m][k] : g[m][k-1220]^2 ; B'(k,j) = W1[1220+k][j]
// =====================================================================
__global__ __launch_bounds__(320) void k_precompute(const float* __restrict__ g,
                                                    const float* __restrict__ W1)
{
    __shared__ __align__(16) float Asm[16][132];    // [k][m]
    __shared__ __align__(16) float Bsm[16][164];    // [k][j]

    const int mtile = blockIdx.x;     // 0..15
    const int slot  = blockIdx.y;     // 0..17
    const int mbase = mtile * 128;

    int kbase, klen, wrow0;
    bool zb;
    if (slot < 6) {
        kbase = slot * 204; klen = min(204, 1220 - kbase); wrow0 = 0;    zb = false;
    } else {
        kbase = (slot - 6) * 204; klen = min(204, 2440 - kbase); wrow0 = 1220; zb = true;
    }

    const int tid = threadIdx.x;
    const int jt  = tid % 20;
    const int mt  = tid / 20;          // 0..15
    const int j0  = jt * 8;
    const int m0  = mt * 8;

    float acc[8][8];
    #pragma unroll
    for (int a = 0; a < 8; ++a)
        #pragma unroll
        for (int b = 0; b < 8; ++b) acc[a][b] = 0.0f;

    for (int kc = 0; kc < klen; kc += 16) {
        // ---- stage B' chunk: 16 rows x 160 cols ----
        {
            int col2 = tid % 80;          // j = 2*col2
            int rb   = tid / 80;          // 0..3
            int j    = col2 * 2;
            #pragma unroll
            for (int it = 0; it < 4; ++it) {
                int row = rb + it * 4;
                float2 v = make_float2(0.0f, 0.0f);
                if ((kc + row) < klen && j < HID) {
                    int wrow = wrow0 + kbase + kc + row;
                    v = *(const float2*)(W1 + wrow * HID + j);
                }
                Bsm[row][j]     = v.x;
                Bsm[row][j + 1] = v.y;
            }
        }
        // ---- stage A' chunk: 128 m x 16 k (transposed into Asm[k][m]) ----
        for (int i = tid; i < 2048; i += 320) {
            int m  = i / 16;
            int kq = i % 16;
            float v = 0.0f;
            if ((mbase + m) < N_SPANS && (kc + kq) < klen) {
                int gk = kbase + kc + kq;
                if (zb && gk >= D_SPAN) {
                    float t = g[(mbase + m) * D_SPAN + (gk - D_SPAN)];
                    v = t * t;
                } else {
                    v = g[(mbase + m) * D_SPAN + gk];
                }
            }
            Asm[kq][m] = v;
        }
        __syncthreads();

        // ---- 8x8 register-tile FMA over 16 k ----
        #pragma unroll
        for (int kk = 0; kk < 16; ++kk) {
            float4 a0 = *(const float4*)&Asm[kk][m0];
            float4 a1 = *(const float4*)&Asm[kk][m0 + 4];
            float4 b0 = *(const float4*)&Bsm[kk][j0];
            float4 b1 = *(const float4*)&Bsm[kk][j0 + 4];
            float av[8] = {a0.x, a0.y, a0.z, a0.w, a1.x, a1.y, a1.z, a1.w};
            float bv[8] = {b0.x, b0.y, b0.z, b0.w, b1.x, b1.y, b1.z, b1.w};
            #pragma unroll
            for (int mm = 0; mm < 8; ++mm)
                #pragma unroll
                for (int jj = 0; jj < 8; ++jj)
                    acc[mm][jj] += av[mm] * bv[jj];
        }
        __syncthreads();
    }

    #pragma unroll
    for (int mm = 0; mm < 8; ++mm) {
        int m = mbase + m0 + mm;
        if (m < N_SPANS) {
            #pragma unroll
            for (int jj = 0; jj < 8; ++jj)
                d_Cpart[slot][m * HPAD + j0 + jj] = acc[mm][jj];
        }
    }
}

// =====================================================================
// K2: reduce k-split partials into TA / TB
// =====================================================================
__global__ void k_reduce()
{
    int idx = blockIdx.x * blockDim.x + threadIdx.x;
    if (idx < N_SPANS * HPAD) {
        float ta = 0.0f, tb = 0.0f;
        #pragma unroll
        for (int s = 0; s < 6; ++s)  ta += d_Cpart[s][idx];
        #pragma unroll
        for (int s = 6; s < 18; ++s) tb += d_Cpart[s][idx];
        d_TA[idx] = ta;
        d_TB[idx] = tb;
    }
}

// =====================================================================
// K3: fused pair kernel with TF32 mma.sync for the h1 @ W2 GEMM.
//   512 blocks x 256 threads (8 warps); 128 pairs / block.
//   stage1: h1 = relu(TA[m]+TB[a]+TPHI[c]) -> H1 smem, tf32 bits, [k][p] stride 136
//   stage2: mma m16n8k8 tf32: warp = (pgroup of 64p) x (jgroup of 40j),
//           4 p-tiles x 5 n-tiles, 19 k-steps (K padded to 152).
//   epilogue: relu(+b2) dot W3, quad-shfl reduce, cross-warp smem reduce.
// =====================================================================
#define KDIM      152
#define H1_STR    136          // ≡ 8 (mod 32): conflict-free fragment loads
#define W2_STR    168          // ≡ 8 (mod 32)
#define OFF_H1    0                            // KDIM*H1_STR = 20672 floats
#define OFF_W2    (KDIM * H1_STR)              // 32*168 = 5376 (aliased by red[512])
#define OFF_W3    (OFF_W2 + 32 * W2_STR)       // 160
#define OFF_B2    (OFF_W3 + HPAD)              // 160
#define OFF_SB    (OFF_B2 + HPAD)              // 128
#define OFF_M     (OFF_SB + 128)
#define OFF_A     (OFF_M + 128)
#define OFF_C     (OFF_A + 128)
#define SMEM_FLOATS (OFF_C + 128)
#define SMEM_BYTES  (SMEM_FLOATS * 4)

__device__ __forceinline__ void mma_tf32(float& c0, float& c1, float& c2, float& c3,
                                         unsigned a0, unsigned a1, unsigned a2, unsigned a3,
                                         unsigned b0, unsigned b1)
{
    asm volatile(
        "mma.sync.aligned.m16n8k8.row.col.f32.tf32.tf32.f32 "
        "{%0,%1,%2,%3}, {%4,%5,%6,%7}, {%8,%9}, {%0,%1,%2,%3};\n"
        : "+f"(c0), "+f"(c1), "+f"(c2), "+f"(c3)
        : "r"(a0), "r"(a1), "r"(a2), "r"(a3), "r"(b0), "r"(b1));
}

__global__ __launch_bounds__(256, 2) void k_pairs(
    const float* __restrict__ s_m, const int* __restrict__ mids,
    const int* __restrict__ aids, const int* __restrict__ dist,
    const int* __restrict__ genre, const int* __restrict__ spk,
    const float* __restrict__ W2, const float* __restrict__ b2,
    const float* __restrict__ W3, const float* __restrict__ b3,
    float* __restrict__ out)
{
    extern __shared__ float S[];
    unsigned* H1  = (unsigned*)(S + OFF_H1);
    unsigned* W2s = (unsigned*)(S + OFF_W2);
    float*    red = S + OFF_W2;   // alias, used after GEMM
    float*    W3s = S + OFF_W3;
    float*    b2s = S + OFF_B2;
    float*    sb  = S + OFF_SB;
    int*      mS  = (int*)(S + OFF_M);
    int*      aS  = (int*)(S + OFF_A);
    int*      cS  = (int*)(S + OFF_C);

    const int tid   = threadIdx.x;
    const int lane  = tid & 31;
    const int wid   = tid >> 5;          // 0..7
    const int pbase = blockIdx.x * 128;

    // ---- per-pair metadata ----
    if (tid < 128) {
        int p = pbase + tid;
        int m = mids[p];
        int a = aids[p];
        mS[tid] = m;
        aS[tid] = a;
        int d = dist[p];
        int bin;
        if      (d >= 64) bin = 8;
        else if (d >= 32) bin = 7;
        else if (d >= 16) bin = 6;
        else if (d >= 8)  bin = 5;
        else if (d >= 5)  bin = 4;
        else              bin = (d >= 1) ? (d - 1) : 0;
        cS[tid] = (bin * 7 + genre[p]) * 3 + spk[p];
        sb[tid] = s_m[m] + s_m[a];
    }
    if (tid < HPAD) {
        float w3v = 0.0f, b2v = 0.0f;
        if (tid < HID) { w3v = W3[tid]; b2v = b2[tid]; }
        W3s[tid] = w3v;
        b2s[tid] = b2v;
    }
    __syncthreads();

    // ---- stage 1: gather + add + relu -> H1[k][p] as tf32 bits ----
    {
        const float4* TA4 = (const float4*)d_TA;
        const float4* TB4 = (const float4*)d_TB;
        const float4* TP4 = (const float4*)d_TPHI;
        for (int idx = tid; idx < 128 * 38; idx += 256) {
            int p = idx & 127;
            int q = idx >> 7;            // 0..37 -> k = 4q..4q+3 < 152
            float4 va = TA4[mS[p] * 40 + q];
            float4 vb = TB4[aS[p] * 40 + q];
            float4 vc = TP4[cS[p] * 40 + q];
            int k = q * 4;
            H1[(k + 0) * H1_STR + p] = f2tf32(fmaxf(va.x + vb.x + vc.x, 0.0f));
            H1[(k + 1) * H1_STR + p] = f2tf32(fmaxf(va.y + vb.y + vc.y, 0.0f));
            H1[(k + 2) * H1_STR + p] = f2tf32(fmaxf(va.z + vb.z + vc.z, 0.0f));
            H1[(k + 3) * H1_STR + p] = f2tf32(fmaxf(va.w + vb.w + vc.w, 0.0f));
        }
    }

    // ---- stage 2: TF32 mma GEMM  h2pre[p][j] = sum_k H1[k][p] * W2[k][j] ----
    const int pg = wid & 1;              // 0..1 : p-group of 64
    const int jg = wid >> 1;             // 0..3 : j-group of 40
    const int pwarp = pg * 64;
    const int jwarp = jg * 40;
    const int lq = lane >> 2;            // 0..7
    const int lr = lane & 3;             // 0..3

    float c[4][5][4];
    #pragma unroll
    for (int pt = 0; pt < 4; ++pt)
        #pragma unroll
        for (int nt = 0; nt < 5; ++nt)
            #pragma unroll
            for (int i = 0; i < 4; ++i) c[pt][nt][i] = 0.0f;

    for (int ch = 0; ch < 5; ++ch) {
        const int rows = min(32, KDIM - ch * 32);   // 32,32,32,32,24
        __syncthreads();                            // H1 done (ch=0) / W2s reuse
        // stage W2 chunk rows [ch*32, ch*32+rows) as tf32 bits
        for (int i = tid; i < rows * 160; i += 256) {
            int row = i / 160;
            int j   = i % 160;
            int gr  = ch * 32 + row;
            float v = (gr < HID && j < HID) ? W2[gr * HID + j] : 0.0f;
            W2s[row * W2_STR + j] = f2tf32(v);
        }
        __syncthreads();

        const int nks = rows >> 3;                  // 4 or 3
        for (int ks = 0; ks < nks; ++ks) {
            const int kc  = ch * 32 + ks * 8;       // global k base
            const int kcs = ks * 8;                 // within-chunk k base
            unsigned bfr[5][2];
            #pragma unroll
            for (int nt = 0; nt < 5; ++nt) {
                int j = jwarp + nt * 8 + lq;
                bfr[nt][0] = W2s[(kcs + lr)     * W2_STR + j];
                bfr[nt][1] = W2s[(kcs + lr + 4) * W2_STR + j];
            }
            #pragma unroll
            for (int pt = 0; pt < 4; ++pt) {
                int p = pwarp + pt * 16 + lq;
                // PTX m16n8k8 A-fragment layout:
                //   a0=(row,col) a1=(row+8,col) a2=(row,col+4) a3=(row+8,col+4)
                unsigned a0 = H1[(kc + lr)     * H1_STR + p];
                unsigned a1 = H1[(kc + lr)     * H1_STR + p + 8];
                unsigned a2 = H1[(kc + lr + 4) * H1_STR + p];
                unsigned a3 = H1[(kc + lr + 4) * H1_STR + p + 8];
                #pragma unroll
                for (int nt = 0; nt < 5; ++nt)
                    mma_tf32(c[pt][nt][0], c[pt][nt][1], c[pt][nt][2], c[pt][nt][3],
                             a0, a1, a2, a3, bfr[nt][0], bfr[nt][1]);
            }
        }
    }

    // ---- epilogue: relu(+b2) dot W3 ----
    float sp[4][2];
    #pragma unroll
    for (int pt = 0; pt < 4; ++pt) { sp[pt][0] = 0.0f; sp[pt][1] = 0.0f; }

    #pragma unroll
    for (int nt = 0; nt < 5; ++nt) {
        int j = jwarp + nt * 8 + 2 * lr;
        float w3a = W3s[j],     b2a = b2s[j];
        float w3b = W3s[j + 1], b2b = b2s[j + 1];
        #pragma unroll
        for (int pt = 0; pt < 4; ++pt) {
            sp[pt][0] += fmaxf(c[pt][nt][0] + b2a, 0.0f) * w3a;
            sp[pt][0] += fmaxf(c[pt][nt][1] + b2b, 0.0f) * w3b;
            sp[pt][1] += fmaxf(c[pt][nt][2] + b2a, 0.0f) * w3a;
            sp[pt][1] += fmaxf(c[pt][nt][3] + b2b, 0.0f) * w3b;
        }
    }
    // reduce across the 4 lanes sharing a p-row (lane%4 varies)
    #pragma unroll
    for (int pt = 0; pt < 4; ++pt) {
        #pragma unroll
        for (int h = 0; h < 2; ++h) {
            sp[pt][h] += __shfl_xor_sync(0xffffffffu, sp[pt][h], 1);
            sp[pt][h] += __shfl_xor_sync(0xffffffffu, sp[pt][h], 2);
        }
    }

    __syncthreads();   // all warps done reading W2s before aliasing as red
    if (lr == 0) {
        #pragma unroll
        for (int pt = 0; pt < 4; ++pt) {
            int p = pwarp + pt * 16 + lq;
            red[jg * 128 + p]     = sp[pt][0];
            red[jg * 128 + p + 8] = sp[pt][1];
        }
    }
    __syncthreads();

    if (tid < 128) {
        float t = red[tid] + red[128 + tid] + red[256 + tid] + red[384 + tid];
        out[pbase + tid] = t + b3[0] + sb[tid];
    }
}

// =====================================================================
// launch
// =====================================================================
extern "C" void kernel_launch(void* const* d_in, const int* in_sizes, int n_in,
                              void* d_out, int out_size)
{
    const float* g    = (const float*)d_in[0];
    const float* s_m  = (const float*)d_in[1];
    const int*   mids = (const int*)d_in[2];
    const int*   aids = (const int*)d_in[3];
    const int*   dist = (const int*)d_in[4];
    const int*   genr = (const int*)d_in[5];
    const int*   spk  = (const int*)d_in[6];
    const float* de   = (const float*)d_in[7];
    const float* ge   = (const float*)d_in[8];
    const float* se   = (const float*)d_in[9];
    const float* W1   = (const float*)d_in[10];
    const float* b1   = (const float*)d_in[11];
    const float* W2   = (const float*)d_in[12];
    const float* b2   = (const float*)d_in[13];
    const float* W3   = (const float*)d_in[14];
    const float* b3   = (const float*)d_in[15];
    float* out = (float*)d_out;

    cudaFuncSetAttribute(k_pairs, cudaFuncAttributeMaxDynamicSharedMemorySize, SMEM_BYTES);

    k_phi<<<NPHI, HPAD>>>(de, ge, se, W1, b1);
    k_precompute<<<dim3(16, 18), 320>>>(g, W1);
    k_reduce<<<(N_SPANS * HPAD + 255) / 256, 256>>>();
    k_pairs<<<NPAIRS / 128, 256, SMEM_BYTES>>>(s_m, mids, aids, dist, genr, spk,
                                               W2, b2, W3, b3, out);
}

// round 4
// speedup vs baseline: 1.8407x; 1.4115x over previous
#include <cuda_runtime.h>
#include <cuda_bf16.h>

// ---------------- problem constants ----------------
#define N_SPANS   2000
#define D_SPAN    1220
#define NPAIRS    65536
#define HID       150
#define HPAD      160          // padded hidden dim (zero-padded 150..159)
#define NPHI      189          // 9 bins * 7 genres * 3 speakers
#define NSLOTS    12           // 4 TA + 4 TB(lin) + 4 TB(sq) k-slots
#define KDIM      152          // padded layer-2 K (19 * 8)

// ---------------- scratch (static device memory; no allocs) ----------------
__device__ __align__(256) float    d_Cpart[NSLOTS][N_SPANS * HPAD];
__device__ __align__(256) float    d_TA[N_SPANS * HPAD];     // g[m] @ W1a
__device__ __align__(256) float    d_TB[N_SPANS * HPAD];     // g[a]@W1b + g[a]^2@W1c
__device__ __align__(256) float    d_TPHI[NPHI * HPAD];      // phi @ W1d + b1
__device__ __align__(256) unsigned d_W2t[KDIM * HPAD];       // W2 as tf32 bits, padded

__device__ __forceinline__ unsigned f2tf32(float x) {
    unsigned r;
    asm("cvt.rna.tf32.f32 %0, %1;" : "=r"(r) : "f"(x));
    return r;
}

__device__ __forceinline__ void mma_tf32(float& c0, float& c1, float& c2, float& c3,
                                         unsigned a0, unsigned a1, unsigned a2, unsigned a3,
                                         unsigned b0, unsigned b1)
{
    asm volatile(
        "mma.sync.aligned.m16n8k8.row.col.f32.tf32.tf32.f32 "
        "{%0,%1,%2,%3}, {%4,%5,%6,%7}, {%8,%9}, {%0,%1,%2,%3};\n"
        : "+f"(c0), "+f"(c1), "+f"(c2), "+f"(c3)
        : "r"(a0), "r"(a1), "r"(a2), "r"(a3), "r"(b0), "r"(b1));
}

// =====================================================================
// K_prep: convert W2 (150x150) -> padded tf32 bits [152][160]
// =====================================================================
__global__ void k_prep(const float* __restrict__ W2)
{
    int idx = blockIdx.x * blockDim.x + threadIdx.x;
    if (idx < KDIM * HPAD) {
        int row = idx / HPAD;
        int j   = idx % HPAD;
        float v = (row < HID && j < HID) ? W2[row * HID + j] : 0.0f;
        d_W2t[idx] = f2tf32(v);
    }
}

// =====================================================================
// K_phi: TPHI[c][j] = b1[j] + phi-embedding combo c @ W1[3660..3719]
// =====================================================================
__global__ void k_phi(const float* __restrict__ de, const float* __restrict__ ge,
                      const float* __restrict__ se, const float* __restrict__ W1,
                      const float* __restrict__ b1)
{
    int c = blockIdx.x;
    int j = threadIdx.x;
    int bin = c / 21;
    int r   = c % 21;
    int gg  = r / 3;
    int ss  = r % 3;
    float v = 0.0f;
    if (j < HID) {
        v = b1[j];
        #pragma unroll
        for (int t = 0; t < 20; ++t) {
            v += de[bin * 20 + t] * W1[(3660 + t) * HID + j];
            v += ge[gg  * 20 + t] * W1[(3680 + t) * HID + j];
            v += se[ss  * 20 + t] * W1[(3700 + t) * HID + j];
        }
    }
    d_TPHI[c * HPAD + j] = v;
}

// =====================================================================
// K1: precompute TA / TB partials with TF32 mma.sync.
//   grid = (16 mtiles, 12 slots), 256 threads (8 warps), BM=128, BN=160.
//   slot 0..3 : TA    over K=1220 (sub-splits {308,308,308,296}), wrow0=0
//   slot 4..7 : TBlin over K=1220 (same splits),                  wrow0=1220
//   slot 8..11: TBsq  over K=1220 (A = g^2),                      wrow0=2440
//   Each slot's K padded to 320 (10 chunks of 32); zero-filled tails.
// =====================================================================
__global__ __launch_bounds__(256) void k_precompute(const float* __restrict__ g,
                                                    const float* __restrict__ W1)
{
    __shared__ __align__(16) unsigned Atf[32][136];   // [k][m] tf32 bits
    __shared__ __align__(16) unsigned Btf[32][168];   // [k][j] tf32 bits

    const int mtile = blockIdx.x;          // 0..15
    const int slot  = blockIdx.y;          // 0..11
    const int mbase = mtile * 128;
    const int sub   = slot & 3;
    const int kbase = sub * 308;
    const int klen  = (sub == 3) ? 296 : 308;
    const int wrow0 = (slot < 4) ? 0 : ((slot < 8) ? 1220 : 2440);
    const bool sq   = (slot >= 8);

    const int tid  = threadIdx.x;
    const int lane = tid & 31;
    const int wid  = tid >> 5;
    const int mg   = wid & 1;              // m-group of 64
    const int jg   = wid >> 1;             // j-group of 40
    const int mwarp = mg * 64;
    const int jwarp = jg * 40;
    const int lq = lane >> 2;
    const int lr = lane & 3;

    float c[4][5][4];
    #pragma unroll
    for (int pt = 0; pt < 4; ++pt)
        #pragma unroll
        for (int nt = 0; nt < 5; ++nt)
            #pragma unroll
            for (int i = 0; i < 4; ++i) c[pt][nt][i] = 0.0f;

    for (int ch = 0; ch < 10; ++ch) {
        const int kc = ch * 32;
        __syncthreads();
        // ---- stage A chunk: 128 m x 32 k -> Atf[k][m] ----
        {
            // 128 m * 8 quads; 4 iterations of 256 threads
            #pragma unroll
            for (int it = 0; it < 4; ++it) {
                int i = it * 256 + tid;
                int m = i & 127;
                int q = i >> 7;                // 0..7
                int kk = kc + q * 4;           // chunk-local k base (mult of 4)
                float4 v = make_float4(0.f, 0.f, 0.f, 0.f);
                if ((mbase + m) < N_SPANS && kk < klen) {
                    v = *(const float4*)(g + (size_t)(mbase + m) * D_SPAN + kbase + kk);
                    if (sq) { v.x *= v.x; v.y *= v.y; v.z *= v.z; v.w *= v.w; }
                }
                Atf[(kk - kc) + 0][m] = f2tf32(v.x);
                Atf[(kk - kc) + 1][m] = f2tf32(v.y);
                Atf[(kk - kc) + 2][m] = f2tf32(v.z);
                Atf[(kk - kc) + 3][m] = f2tf32(v.w);
            }
        }
        // ---- stage B chunk: 32 k x 160 j -> Btf[k][j] ----
        {
            // 32 rows * 80 float2-cols; 10 iterations
            #pragma unroll
            for (int it = 0; it < 10; ++it) {
                int i = it * 256 + tid;        // 0..2559
                int row = i / 80;
                int q   = i % 80;
                int j   = q * 2;
                float2 v = make_float2(0.f, 0.f);
                int kk = kc + row;
                if (kk < klen && j < HID)
                    v = *(const float2*)(W1 + (size_t)(wrow0 + kbase + kk) * HID + j);
                Btf[row][j]     = f2tf32(v.x);
                Btf[row][j + 1] = f2tf32(v.y);
            }
        }
        __syncthreads();

        // ---- 4 k-steps of mma ----
        #pragma unroll
        for (int ks = 0; ks < 4; ++ks) {
            const int kcs = ks * 8;
            unsigned bfr[5][2];
            #pragma unroll
            for (int nt = 0; nt < 5; ++nt) {
                int j = jwarp + nt * 8 + lq;
                bfr[nt][0] = Btf[kcs + lr][j];
                bfr[nt][1] = Btf[kcs + lr + 4][j];
            }
            #pragma unroll
            for (int pt = 0; pt < 4; ++pt) {
                int m = mwarp + pt * 16 + lq;
                unsigned a0 = Atf[kcs + lr][m];
                unsigned a1 = Atf[kcs + lr][m + 8];
                unsigned a2 = Atf[kcs + lr + 4][m];
                unsigned a3 = Atf[kcs + lr + 4][m + 8];
                #pragma unroll
                for (int nt = 0; nt < 5; ++nt)
                    mma_tf32(c[pt][nt][0], c[pt][nt][1], c[pt][nt][2], c[pt][nt][3],
                             a0, a1, a2, a3, bfr[nt][0], bfr[nt][1]);
            }
        }
    }

    // ---- write partials ----
    float* dst = d_Cpart[slot];
    #pragma unroll
    for (int pt = 0; pt < 4; ++pt) {
        int m0 = mbase + mwarp + pt * 16 + lq;
        #pragma unroll
        for (int nt = 0; nt < 5; ++nt) {
            int j = jwarp + nt * 8 + 2 * lr;
            if (m0 < N_SPANS)
                *(float2*)(dst + (size_t)m0 * HPAD + j) = make_float2(c[pt][nt][0], c[pt][nt][1]);
            if (m0 + 8 < N_SPANS)
                *(float2*)(dst + (size_t)(m0 + 8) * HPAD + j) = make_float2(c[pt][nt][2], c[pt][nt][3]);
        }
    }
}

// =====================================================================
// K2: reduce k-split partials into TA / TB
// =====================================================================
__global__ void k_reduce()
{
    int idx = blockIdx.x * blockDim.x + threadIdx.x;
    if (idx < N_SPANS * HPAD) {
        float ta = 0.0f, tb = 0.0f;
        #pragma unroll
        for (int s = 0; s < 4; ++s)  ta += d_Cpart[s][idx];
        #pragma unroll
        for (int s = 4; s < 12; ++s) tb += d_Cpart[s][idx];
        d_TA[idx] = ta;
        d_TB[idx] = tb;
    }
}

// =====================================================================
// K3: fused pair kernel with TF32 mma.sync for the h1 @ W2 GEMM.
// =====================================================================
#define H1_STR    136          // ≡ 8 (mod 32)
#define W2_STR    168          // ≡ 8 (mod 32)
#define OFF_H1    0                            // KDIM*H1_STR floats
#define OFF_W2    (KDIM * H1_STR)              // 32*168 (aliased by red[512])
#define OFF_W3    (OFF_W2 + 32 * W2_STR)
#define OFF_B2    (OFF_W3 + HPAD)
#define OFF_SB    (OFF_B2 + HPAD)
#define OFF_M     (OFF_SB + 128)
#define OFF_A     (OFF_M + 128)
#define OFF_C     (OFF_A + 128)
#define SMEM_FLOATS (OFF_C + 128)
#define SMEM_BYTES  (SMEM_FLOATS * 4)

__global__ __launch_bounds__(256, 2) void k_pairs(
    const float* __restrict__ s_m, const int* __restrict__ mids,
    const int* __restrict__ aids, const int* __restrict__ dist,
    const int* __restrict__ genre, const int* __restrict__ spk,
    const float* __restrict__ b2, const float* __restrict__ W3,
    const float* __restrict__ b3, float* __restrict__ out)
{
    extern __shared__ float S[];
    unsigned* H1  = (unsigned*)(S + OFF_H1);
    unsigned* W2s = (unsigned*)(S + OFF_W2);
    float*    red = S + OFF_W2;   // alias, used after GEMM
    float*    W3s = S + OFF_W3;
    float*    b2s = S + OFF_B2;
    float*    sb  = S + OFF_SB;
    int*      mS  = (int*)(S + OFF_M);
    int*      aS  = (int*)(S + OFF_A);
    int*      cS  = (int*)(S + OFF_C);

    const int tid   = threadIdx.x;
    const int lane  = tid & 31;
    const int wid   = tid >> 5;
    const int pbase = blockIdx.x * 128;

    // ---- per-pair metadata ----
    if (tid < 128) {
        int p = pbase + tid;
        int m = mids[p];
        int a = aids[p];
        mS[tid] = m;
        aS[tid] = a;
        int d = dist[p];
        int bin;
        if      (d >= 64) bin = 8;
        else if (d >= 32) bin = 7;
        else if (d >= 16) bin = 6;
        else if (d >= 8)  bin = 5;
        else if (d >= 5)  bin = 4;
        else              bin = (d >= 1) ? (d - 1) : 0;
        cS[tid] = (bin * 7 + genre[p]) * 3 + spk[p];
        sb[tid] = s_m[m] + s_m[a];
    }
    if (tid < HPAD) {
        float w3v = 0.0f, b2v = 0.0f;
        if (tid < HID) { w3v = W3[tid]; b2v = b2[tid]; }
        W3s[tid] = w3v;
        b2s[tid] = b2v;
    }
    __syncthreads();

    // ---- stage 1: gather + add + relu -> H1[k][p] as tf32 bits ----
    {
        const float4* TA4 = (const float4*)d_TA;
        const float4* TB4 = (const float4*)d_TB;
        const float4* TP4 = (const float4*)d_TPHI;
        for (int idx = tid; idx < 128 * 38; idx += 256) {
            int p = idx & 127;
            int q = idx >> 7;            // 0..37 -> k = 4q..4q+3 < 152
            float4 va = TA4[mS[p] * 40 + q];
            float4 vb = TB4[aS[p] * 40 + q];
            float4 vc = TP4[cS[p] * 40 + q];
            int k = q * 4;
            H1[(k + 0) * H1_STR + p] = f2tf32(fmaxf(va.x + vb.x + vc.x, 0.0f));
            H1[(k + 1) * H1_STR + p] = f2tf32(fmaxf(va.y + vb.y + vc.y, 0.0f));
            H1[(k + 2) * H1_STR + p] = f2tf32(fmaxf(va.z + vb.z + vc.z, 0.0f));
            H1[(k + 3) * H1_STR + p] = f2tf32(fmaxf(va.w + vb.w + vc.w, 0.0f));
        }
    }

    // ---- stage 2: TF32 mma GEMM ----
    const int pg = wid & 1;
    const int jg = wid >> 1;
    const int pwarp = pg * 64;
    const int jwarp = jg * 40;
    const int lq = lane >> 2;
    const int lr = lane & 3;

    float c[4][5][4];
    #pragma unroll
    for (int pt = 0; pt < 4; ++pt)
        #pragma unroll
        for (int nt = 0; nt < 5; ++nt)
            #pragma unroll
            for (int i = 0; i < 4; ++i) c[pt][nt][i] = 0.0f;

    for (int ch = 0; ch < 5; ++ch) {
        const int rows = min(32, KDIM - ch * 32);   // 32,32,32,32,24
        __syncthreads();
        // stage W2 chunk: pure uint4 copy of pre-converted tf32 bits
        for (int i4 = tid; i4 < rows * 40; i4 += 256) {
            int row = i4 / 40;
            int j   = (i4 % 40) * 4;
            uint4 v = *(const uint4*)(d_W2t + (ch * 32 + row) * HPAD + j);
            *(uint4*)(W2s + row * W2_STR + j) = v;
        }
        __syncthreads();

        const int nks = rows >> 3;
        for (int ks = 0; ks < nks; ++ks) {
            const int kc  = ch * 32 + ks * 8;
            const int kcs = ks * 8;
            unsigned bfr[5][2];
            #pragma unroll
            for (int nt = 0; nt < 5; ++nt) {
                int j = jwarp + nt * 8 + lq;
                bfr[nt][0] = W2s[(kcs + lr)     * W2_STR + j];
                bfr[nt][1] = W2s[(kcs + lr + 4) * W2_STR + j];
            }
            #pragma unroll
            for (int pt = 0; pt < 4; ++pt) {
                int p = pwarp + pt * 16 + lq;
                unsigned a0 = H1[(kc + lr)     * H1_STR + p];
                unsigned a1 = H1[(kc + lr)     * H1_STR + p + 8];
                unsigned a2 = H1[(kc + lr + 4) * H1_STR + p];
                unsigned a3 = H1[(kc + lr + 4) * H1_STR + p + 8];
                #pragma unroll
                for (int nt = 0; nt < 5; ++nt)
                    mma_tf32(c[pt][nt][0], c[pt][nt][1], c[pt][nt][2], c[pt][nt][3],
                             a0, a1, a2, a3, bfr[nt][0], bfr[nt][1]);
            }
        }
    }

    // ---- epilogue: relu(+b2) dot W3 ----
    float sp[4][2];
    #pragma unroll
    for (int pt = 0; pt < 4; ++pt) { sp[pt][0] = 0.0f; sp[pt][1] = 0.0f; }

    #pragma unroll
    for (int nt = 0; nt < 5; ++nt) {
        int j = jwarp + nt * 8 + 2 * lr;
        float w3a = W3s[j],     b2a = b2s[j];
        float w3b = W3s[j + 1], b2b = b2s[j + 1];
        #pragma unroll
        for (int pt = 0; pt < 4; ++pt) {
            sp[pt][0] += fmaxf(c[pt][nt][0] + b2a, 0.0f) * w3a;
            sp[pt][0] += fmaxf(c[pt][nt][1] + b2b, 0.0f) * w3b;
            sp[pt][1] += fmaxf(c[pt][nt][2] + b2a, 0.0f) * w3a;
            sp[pt][1] += fmaxf(c[pt][nt][3] + b2b, 0.0f) * w3b;
        }
    }
    #pragma unroll
    for (int pt = 0; pt < 4; ++pt) {
        #pragma unroll
        for (int h = 0; h < 2; ++h) {
            sp[pt][h] += __shfl_xor_sync(0xffffffffu, sp[pt][h], 1);
            sp[pt][h] += __shfl_xor_sync(0xffffffffu, sp[pt][h], 2);
        }
    }

    __syncthreads();
    if (lr == 0) {
        #pragma unroll
        for (int pt = 0; pt < 4; ++pt) {
            int p = pwarp + pt * 16 + lq;
            red[jg * 128 + p]     = sp[pt][0];
            red[jg * 128 + p + 8] = sp[pt][1];
        }
    }
    __syncthreads();

    if (tid < 128) {
        float t = red[tid] + red[128 + tid] + red[256 + tid] + red[384 + tid];
        out[pbase + tid] = t + b3[0] + sb[tid];
    }
}

// =====================================================================
// launch
// =====================================================================
extern "C" void kernel_launch(void* const* d_in, const int* in_sizes, int n_in,
                              void* d_out, int out_size)
{
    const float* g    = (const float*)d_in[0];
    const float* s_m  = (const float*)d_in[1];
    const int*   mids = (const int*)d_in[2];
    const int*   aids = (const int*)d_in[3];
    const int*   dist = (const int*)d_in[4];
    const int*   genr = (const int*)d_in[5];
    const int*   spk  = (const int*)d_in[6];
    const float* de   = (const float*)d_in[7];
    const float* ge   = (const float*)d_in[8];
    const float* se   = (const float*)d_in[9];
    const float* W1   = (const float*)d_in[10];
    const float* b1   = (const float*)d_in[11];
    const float* W2   = (const float*)d_in[12];
    const float* b2   = (const float*)d_in[13];
    const float* W3   = (const float*)d_in[14];
    const float* b3   = (const float*)d_in[15];
    float* out = (float*)d_out;

    cudaFuncSetAttribute(k_pairs, cudaFuncAttributeMaxDynamicSharedMemorySize, SMEM_BYTES);

    k_prep<<<(KDIM * HPAD + 255) / 256, 256>>>(W2);
    k_phi<<<NPHI, HPAD>>>(de, ge, se, W1, b1);
    k_precompute<<<dim3(16, NSLOTS), 256>>>(g, W1);
    k_reduce<<<(N_SPANS * HPAD + 255) / 256, 256>>>();
    k_pairs<<<NPAIRS / 128, 256, SMEM_BYTES>>>(s_m, mids, aids, dist, genr, spk,
                                               b2, W3, b3, out);
}

// round 5
// speedup vs baseline: 2.5355x; 1.3774x over previous
#include <cuda_runtime.h>
#include <cuda_bf16.h>

// ---------------- problem constants ----------------
#define N_SPANS   2000
#define D_SPAN    1220
#define NPAIRS    65536
#define HID       150
#define HPAD      160          // padded hidden dim (zero-padded 150..159)
#define NPHI      189          // 9 bins * 7 genres * 3 speakers
#define NSLOTS    12           // 4 TA + 4 TB(lin) + 4 TB(sq) k-slots
#define KDIM      152          // padded layer-2 K (19 * 8)

// ---------------- scratch (static device memory; no allocs) ----------------
__device__ __align__(256) float    d_Cpart[NSLOTS][N_SPANS * HPAD];
__device__ __align__(256) float    d_TA[N_SPANS * HPAD];     // g[m] @ W1a
__device__ __align__(256) float    d_TB[N_SPANS * HPAD];     // g[a]@W1b + g[a]^2@W1c
__device__ __align__(256) float    d_TPHI[NPHI * HPAD];      // phi @ W1d + b1
__device__ __align__(256) unsigned d_W2t[KDIM * HPAD];       // W2 as tf32 bits, padded

__device__ __forceinline__ unsigned f2tf32(float x) {
    unsigned r;
    asm("cvt.rna.tf32.f32 %0, %1;" : "=r"(r) : "f"(x));
    return r;
}

__device__ __forceinline__ void mma_tf32(float& c0, float& c1, float& c2, float& c3,
                                         unsigned a0, unsigned a1, unsigned a2, unsigned a3,
                                         unsigned b0, unsigned b1)
{
    asm volatile(
        "mma.sync.aligned.m16n8k8.row.col.f32.tf32.tf32.f32 "
        "{%0,%1,%2,%3}, {%4,%5,%6,%7}, {%8,%9}, {%0,%1,%2,%3};\n"
        : "+f"(c0), "+f"(c1), "+f"(c2), "+f"(c3)
        : "r"(a0), "r"(a1), "r"(a2), "r"(a3), "r"(b0), "r"(b1));
}

__device__ __forceinline__ void cpa16(unsigned dst, const void* src, int srcsize) {
    asm volatile("cp.async.ca.shared.global [%0], [%1], 16, %2;\n"
                 :: "r"(dst), "l"(src), "r"(srcsize));
}
__device__ __forceinline__ void cpa8(unsigned dst, const void* src, int srcsize) {
    asm volatile("cp.async.ca.shared.global [%0], [%1], 8, %2;\n"
                 :: "r"(dst), "l"(src), "r"(srcsize));
}
__device__ __forceinline__ void cpa_commit() {
    asm volatile("cp.async.commit_group;\n");
}
__device__ __forceinline__ void cpa_wait0() {
    asm volatile("cp.async.wait_group 0;\n");
}

// =====================================================================
// K_prep: convert W2 (150x150) -> padded tf32 bits [152][160]
// =====================================================================
__global__ void k_prep(const float* __restrict__ W2)
{
    int idx = blockIdx.x * blockDim.x + threadIdx.x;
    if (idx < KDIM * HPAD) {
        int row = idx / HPAD;
        int j   = idx % HPAD;
        float v = (row < HID && j < HID) ? W2[row * HID + j] : 0.0f;
        d_W2t[idx] = f2tf32(v);
    }
}

// =====================================================================
// K_phi: TPHI[c][j] = b1[j] + phi-embedding combo c @ W1[3660..3719]
// =====================================================================
__global__ void k_phi(const float* __restrict__ de, const float* __restrict__ ge,
                      const float* __restrict__ se, const float* __restrict__ W1,
                      const float* __restrict__ b1)
{
    int c = blockIdx.x;
    int j = threadIdx.x;
    int bin = c / 21;
    int r   = c % 21;
    int gg  = r / 3;
    int ss  = r % 3;
    float v = 0.0f;
    if (j < HID) {
        v = b1[j];
        #pragma unroll
        for (int t = 0; t < 20; ++t) {
            v += de[bin * 20 + t] * W1[(3660 + t) * HID + j];
            v += ge[gg  * 20 + t] * W1[(3680 + t) * HID + j];
            v += se[ss  * 20 + t] * W1[(3700 + t) * HID + j];
        }
    }
    d_TPHI[c * HPAD + j] = v;
}

// =====================================================================
// K1: precompute TA / TB partials with TF32 mma, cp.async staging,
//     single-sync double-buffered chunk pipeline.
//   grid = (16 mtiles, 12 slots), 256 threads, BM=128, BN=160.
//   slot 0..3 : TA    (A = g,   B rows = W1[0..1220))
//   slot 4..7 : TBlin (A = g,   B rows = W1[1220..2440))
//   slot 8..11: TBsq  (A = g^2, B rows = W1[2440..3660))
//   K per slot: {308,308,308,296}, padded to 320 = 10 chunks of 32.
//   Atf: [m][k] stride 36 (tf32/raw-fp32 bits). Btf: [k][j] stride 168.
// =====================================================================
#define PRE_ATF_W   (2 * 128 * 36)     // 9216 words
#define PRE_BTF_W   (2 * 32 * 168)     // 10752 words
#define PRE_SMEM_W  (PRE_ATF_W + PRE_BTF_W)
#define PRE_SMEM_B  (PRE_SMEM_W * 4)

__global__ __launch_bounds__(256, 2) void k_precompute(const float* __restrict__ g,
                                                       const float* __restrict__ W1)
{
    extern __shared__ unsigned SP[];
    unsigned* Atf = SP;                 // 2 buffers of [128][36]
    unsigned* Btf = SP + PRE_ATF_W;     // 2 buffers of [32][168]

    const int mtile = blockIdx.x;          // 0..15
    const int slot  = blockIdx.y;          // 0..11
    const int mbase = mtile * 128;
    const int sub   = slot & 3;
    const int kbase = sub * 308;
    const int klen  = (sub == 3) ? 296 : 308;   // multiple of 4
    const int wrow0 = (slot < 4) ? 0 : ((slot < 8) ? 1220 : 2440);
    const bool sq   = (slot >= 8);

    const int tid  = threadIdx.x;
    const int lane = tid & 31;
    const int wid  = tid >> 5;
    const int mwarp = (wid & 1) * 64;
    const int jwarp = (wid >> 1) * 40;
    const int lq = lane >> 2;
    const int lr = lane & 3;

    // staging maps (fixed per thread)
    const int am = tid >> 3;            // A: row group base (m = am + 32*it)
    const int aq = tid & 7;             // A: 16B quad within row
    const int brow = tid >> 3;          // B: k-row 0..31
    const int bj   = tid & 7;           // B: j2 = bj + 8*s

    unsigned a_smem_base = (unsigned)__cvta_generic_to_shared(Atf);
    unsigned b_smem_base = (unsigned)__cvta_generic_to_shared(Btf);

    float c[4][5][4];
    #pragma unroll
    for (int pt = 0; pt < 4; ++pt)
        #pragma unroll
        for (int nt = 0; nt < 5; ++nt)
            #pragma unroll
            for (int i = 0; i < 4; ++i) c[pt][nt][i] = 0.0f;

    // ---------- staging lambdas ----------
    auto stageA = [&](int ch, int bsel) {
        unsigned abase = a_smem_base + bsel * (128 * 36 * 4);
        if (!sq) {
            #pragma unroll
            for (int it = 0; it < 4; ++it) {
                int m  = am + it * 32;
                int kk = ch * 32 + aq * 4;
                int ok = ((mbase + m) < N_SPANS && kk < klen) ? 16 : 0;
                const float* src = g + (size_t)(mbase + (ok ? m : 0)) * D_SPAN
                                     + (ok ? (kbase + kk) : 0);
                cpa16(abase + (m * 36 + aq * 4) * 4, src, ok);
            }
        } else {
            unsigned* ab = (unsigned*)Atf + bsel * (128 * 36);
            #pragma unroll
            for (int it = 0; it < 4; ++it) {
                int m  = am + it * 32;
                int kk = ch * 32 + aq * 4;
                float4 v = make_float4(0.f, 0.f, 0.f, 0.f);
                if ((mbase + m) < N_SPANS && kk < klen)
                    v = *(const float4*)(g + (size_t)(mbase + m) * D_SPAN + kbase + kk);
                uint4 o;
                o.x = f2tf32(v.x * v.x);
                o.y = f2tf32(v.y * v.y);
                o.z = f2tf32(v.z * v.z);
                o.w = f2tf32(v.w * v.w);
                *(uint4*)(ab + m * 36 + aq * 4) = o;
            }
        }
    };
    auto stageB = [&](int ch, int bsel) {
        unsigned bbase = b_smem_base + bsel * (32 * 168 * 4);
        int kk = ch * 32 + brow;
        const float* rowp = W1 + (size_t)(wrow0 + kbase + ((kk < klen) ? kk : 0)) * HID;
        #pragma unroll
        for (int s = 0; s < 10; ++s) {
            int j2 = bj + 8 * s;        // 0..79
            int ok = (kk < klen && j2 < 75) ? 8 : 0;
            cpa8(bbase + (brow * 168 + j2 * 2) * 4, rowp + (ok ? j2 * 2 : 0), ok);
        }
    };

    // ---------- pipeline ----------
    stageA(0, 0);
    stageB(0, 0);
    cpa_commit();

    for (int ch = 0; ch < 10; ++ch) {
        const int buf = ch & 1;
        cpa_wait0();
        __syncthreads();
        if (ch < 9) {
            stageA(ch + 1, buf ^ 1);
            stageB(ch + 1, buf ^ 1);
            cpa_commit();
        }
        const unsigned* Ab = (const unsigned*)Atf + buf * (128 * 36);
        const unsigned* Bb = (const unsigned*)Btf + buf * (32 * 168);
        #pragma unroll
        for (int ks = 0; ks < 4; ++ks) {
            const int kcs = ks * 8;
            unsigned bfr[5][2];
            #pragma unroll
            for (int nt = 0; nt < 5; ++nt) {
                int j = jwarp + nt * 8 + lq;
                bfr[nt][0] = Bb[(kcs + lr)     * 168 + j];
                bfr[nt][1] = Bb[(kcs + lr + 4) * 168 + j];
            }
            #pragma unroll
            for (int pt = 0; pt < 4; ++pt) {
                int m = mwarp + pt * 16 + lq;
                unsigned a0 = Ab[m       * 36 + kcs + lr];
                unsigned a1 = Ab[(m + 8) * 36 + kcs + lr];
                unsigned a2 = Ab[m       * 36 + kcs + lr + 4];
                unsigned a3 = Ab[(m + 8) * 36 + kcs + lr + 4];
                #pragma unroll
                for (int nt = 0; nt < 5; ++nt)
                    mma_tf32(c[pt][nt][0], c[pt][nt][1], c[pt][nt][2], c[pt][nt][3],
                             a0, a1, a2, a3, bfr[nt][0], bfr[nt][1]);
            }
        }
    }

    // ---- write partials ----
    float* dst = d_Cpart[slot];
    #pragma unroll
    for (int pt = 0; pt < 4; ++pt) {
        int m0 = mbase + mwarp + pt * 16 + lq;
        #pragma unroll
        for (int nt = 0; nt < 5; ++nt) {
            int j = jwarp + nt * 8 + 2 * lr;
            if (m0 < N_SPANS)
                *(float2*)(dst + (size_t)m0 * HPAD + j) = make_float2(c[pt][nt][0], c[pt][nt][1]);
            if (m0 + 8 < N_SPANS)
                *(float2*)(dst + (size_t)(m0 + 8) * HPAD + j) = make_float2(c[pt][nt][2], c[pt][nt][3]);
        }
    }
}

// =====================================================================
// K2: reduce k-split partials into TA / TB (float4)
// =====================================================================
__global__ void k_reduce()
{
    int idx = blockIdx.x * blockDim.x + threadIdx.x;
    if (idx < N_SPANS * HPAD / 4) {
        float4 ta = make_float4(0.f, 0.f, 0.f, 0.f);
        float4 tb = ta;
        #pragma unroll
        for (int s = 0; s < 4; ++s) {
            float4 v = ((const float4*)d_Cpart[s])[idx];
            ta.x += v.x; ta.y += v.y; ta.z += v.z; ta.w += v.w;
        }
        #pragma unroll
        for (int s = 4; s < 12; ++s) {
            float4 v = ((const float4*)d_Cpart[s])[idx];
            tb.x += v.x; tb.y += v.y; tb.z += v.z; tb.w += v.w;
        }
        ((float4*)d_TA)[idx] = ta;
        ((float4*)d_TB)[idx] = tb;
    }
}

// =====================================================================
// K3: fused pair kernel, single-sync double-buffered chunk pipeline.
//   512 blocks x 256 threads; 128 pairs / block.
//   H1 chunk buffers [p][k] stride 36 (STS.128 + frag loads conflict-free).
//   W2 chunk buffers [k][j] stride 168 via cp.async of pre-converted bits.
// =====================================================================
#define KP_HB_W   (2 * 128 * 36)       // 9216 words
#define KP_WB_W   (2 * 32 * 168)       // 10752 words
#define KP_OFF_W3 (KP_HB_W + KP_WB_W)  // 19968
#define KP_OFF_B2 (KP_OFF_W3 + HPAD)
#define KP_SMEM_W (KP_OFF_B2 + HPAD)
#define KP_SMEM_B (KP_SMEM_W * 4)

__global__ __launch_bounds__(256, 2) void k_pairs(
    const float* __restrict__ s_m, const int* __restrict__ mids,
    const int* __restrict__ aids, const int* __restrict__ dist,
    const int* __restrict__ genre, const int* __restrict__ spk,
    const float* __restrict__ W3, const float* __restrict__ b2,
    const float* __restrict__ b3, float* __restrict__ out)
{
    extern __shared__ unsigned SU[];
    unsigned* Hb  = SU;                       // 2 x [128][36]
    unsigned* Wb  = SU + KP_HB_W;             // 2 x [32][168]
    float*    W3s = (float*)(SU + KP_OFF_W3);
    float*    b2s = (float*)(SU + KP_OFF_B2);
    float*    red = (float*)(Wb + 32 * 168);  // alias buffer 1 of Wb (last MMA uses buf 0)

    const int tid   = threadIdx.x;
    const int lane  = tid & 31;
    const int wid   = tid >> 5;
    const int pbase = blockIdx.x * 128;
    const int pl    = tid & 127;
    const int qoff  = tid >> 7;               // 0 or 1

    // ---- per-thread pair metadata (no smem) ----
    const int p = pbase + pl;
    const int m = mids[p];
    const int a = aids[p];
    int d = dist[p];
    int bin;
    if      (d >= 64) bin = 8;
    else if (d >= 32) bin = 7;
    else if (d >= 16) bin = 6;
    else if (d >= 8)  bin = 5;
    else if (d >= 5)  bin = 4;
    else              bin = (d >= 1) ? (d - 1) : 0;
    const int cphi = (bin * 7 + genre[p]) * 3 + spk[p];
    const float sbv = s_m[m] + s_m[a];

    const float4* Am = (const float4*)d_TA  + (size_t)m * 40;
    const float4* Bm = (const float4*)d_TB  + (size_t)a * 40;
    const float4* Cm = (const float4*)d_TPHI + (size_t)cphi * 40;

    if (tid < HPAD) {
        float w3v = 0.0f, b2v = 0.0f;
        if (tid < HID) { w3v = W3[tid]; b2v = b2[tid]; }
        W3s[tid] = w3v;
        b2s[tid] = b2v;
    }

    unsigned w_smem_base = (unsigned)__cvta_generic_to_shared(Wb);

    // ---- staging helpers ----
    auto stageW2 = [&](int ch, int bsel) {
        unsigned wb = w_smem_base + bsel * (32 * 168 * 4);
        const int rows = (ch == 4) ? 24 : 32;
        for (int i4 = tid; i4 < rows * 40; i4 += 256) {
            int row = i4 / 40;
            int j4  = i4 - row * 40;
            cpa16(wb + (row * 168 + j4 * 4) * 4,
                  d_W2t + (ch * 32 + row) * HPAD + j4 * 4, 16);
        }
    };
    auto gather = [&](int ch, int bsel) {
        unsigned* hb = Hb + bsel * (128 * 36);
        const int rmax = (ch == 4) ? 3 : 4;
        int q = ch * 8 + qoff;
        float4 va = Am[q], vb = Bm[q], vc = Cm[q];
        #pragma unroll
        for (int r = 0; r < 4; ++r) {
            if (r >= rmax) break;
            uint4 o;
            o.x = f2tf32(fmaxf(va.x + vb.x + vc.x, 0.0f));
            o.y = f2tf32(fmaxf(va.y + vb.y + vc.y, 0.0f));
            o.z = f2tf32(fmaxf(va.z + vb.z + vc.z, 0.0f));
            o.w = f2tf32(fmaxf(va.w + vb.w + vc.w, 0.0f));
            if (r + 1 < rmax) {
                int qn = q + 2;
                va = Am[qn]; vb = Bm[qn]; vc = Cm[qn];
            }
            *(uint4*)(hb + pl * 36 + (qoff + 2 * r) * 4) = o;
            q += 2;
        }
    };

    // ---- MMA tiling ----
    const int pwarp = (wid & 1) * 64;
    const int jwarp = (wid >> 1) * 40;
    const int lq = lane >> 2;
    const int lr = lane & 3;

    float c[4][5][4];
    #pragma unroll
    for (int pt = 0; pt < 4; ++pt)
        #pragma unroll
        for (int nt = 0; nt < 5; ++nt)
            #pragma unroll
            for (int i = 0; i < 4; ++i) c[pt][nt][i] = 0.0f;

    // ---- pipeline ----
    stageW2(0, 0);
    cpa_commit();
    gather(0, 0);

    for (int ch = 0; ch < 5; ++ch) {
        const int buf = ch & 1;
        cpa_wait0();
        __syncthreads();
        if (ch < 4) {
            stageW2(ch + 1, buf ^ 1);
            cpa_commit();
            gather(ch + 1, buf ^ 1);
        }
        const unsigned* hb = Hb + buf * (128 * 36);
        const unsigned* wb = Wb + buf * (32 * 168);
        const int nks = (ch == 4) ? 3 : 4;
        for (int ks = 0; ks < nks; ++ks) {
            const int kcs = ks * 8;
            unsigned bfr[5][2];
            #pragma unroll
            for (int nt = 0; nt < 5; ++nt) {
                int j = jwarp + nt * 8 + lq;
                bfr[nt][0] = wb[(kcs + lr)     * 168 + j];
                bfr[nt][1] = wb[(kcs + lr + 4) * 168 + j];
            }
            #pragma unroll
            for (int pt = 0; pt < 4; ++pt) {
                int pp = pwarp + pt * 16 + lq;
                unsigned a0 = hb[pp       * 36 + kcs + lr];
                unsigned a1 = hb[(pp + 8) * 36 + kcs + lr];
                unsigned a2 = hb[pp       * 36 + kcs + lr + 4];
                unsigned a3 = hb[(pp + 8) * 36 + kcs + lr + 4];
                #pragma unroll
                for (int nt = 0; nt < 5; ++nt)
                    mma_tf32(c[pt][nt][0], c[pt][nt][1], c[pt][nt][2], c[pt][nt][3],
                             a0, a1, a2, a3, bfr[nt][0], bfr[nt][1]);
            }
        }
    }

    // ---- epilogue: relu(+b2) dot W3 ----
    float sp[4][2];
    #pragma unroll
    for (int pt = 0; pt < 4; ++pt) { sp[pt][0] = 0.0f; sp[pt][1] = 0.0f; }

    #pragma unroll
    for (int nt = 0; nt < 5; ++nt) {
        int j = jwarp + nt * 8 + 2 * lr;
        float w3a = W3s[j],     b2a = b2s[j];
        float w3b = W3s[j + 1], b2b = b2s[j + 1];
        #pragma unroll
        for (int pt = 0; pt < 4; ++pt) {
            sp[pt][0] += fmaxf(c[pt][nt][0] + b2a, 0.0f) * w3a;
            sp[pt][0] += fmaxf(c[pt][nt][1] + b2b, 0.0f) * w3b;
            sp[pt][1] += fmaxf(c[pt][nt][2] + b2a, 0.0f) * w3a;
            sp[pt][1] += fmaxf(c[pt][nt][3] + b2b, 0.0f) * w3b;
        }
    }
    #pragma unroll
    for (int pt = 0; pt < 4; ++pt) {
        #pragma unroll
        for (int h = 0; h < 2; ++h) {
            sp[pt][h] += __shfl_xor_sync(0xffffffffu, sp[pt][h], 1);
            sp[pt][h] += __shfl_xor_sync(0xffffffffu, sp[pt][h], 2);
        }
    }

    // red aliases Wb buffer 1 (last MMA chunk used buffer 0; buffer 1 reads
    // finished before the ch=4 top-of-loop barrier)
    const int jg = wid >> 1;
    if (lr == 0) {
        #pragma unroll
        for (int pt = 0; pt < 4; ++pt) {
            int pp = pwarp + pt * 16 + lq;
            red[jg * 128 + pp]     = sp[pt][0];
            red[jg * 128 + pp + 8] = sp[pt][1];
        }
    }
    __syncthreads();

    if (tid < 128) {
        float t = red[tid] + red[128 + tid] + red[256 + tid] + red[384 + tid];
        out[pbase + tid] = t + b3[0] + sbv;
    }
}

// =====================================================================
// launch
// =====================================================================
extern "C" void kernel_launch(void* const* d_in, const int* in_sizes, int n_in,
                              void* d_out, int out_size)
{
    const float* g    = (const float*)d_in[0];
    const float* s_m  = (const float*)d_in[1];
    const int*   mids = (const int*)d_in[2];
    const int*   aids = (const int*)d_in[3];
    const int*   dist = (const int*)d_in[4];
    const int*   genr = (const int*)d_in[5];
    const int*   spk  = (const int*)d_in[6];
    const float* de   = (const float*)d_in[7];
    const float* ge   = (const float*)d_in[8];
    const float* se   = (const float*)d_in[9];
    const float* W1   = (const float*)d_in[10];
    const float* b1   = (const float*)d_in[11];
    const float* W2   = (const float*)d_in[12];
    const float* b2   = (const float*)d_in[13];
    const float* W3   = (const float*)d_in[14];
    const float* b3   = (const float*)d_in[15];
    float* out = (float*)d_out;

    static int attr_done = 0;
    if (!attr_done) {
        cudaFuncSetAttribute(k_precompute, cudaFuncAttributeMaxDynamicSharedMemorySize, PRE_SMEM_B);
        cudaFuncSetAttribute(k_pairs, cudaFuncAttributeMaxDynamicSharedMemorySize, KP_SMEM_B);
        attr_done = 1;
    }

    k_prep<<<(KDIM * HPAD + 255) / 256, 256>>>(W2);
    k_phi<<<NPHI, HPAD>>>(de, ge, se, W1, b1);
    k_precompute<<<dim3(16, NSLOTS), 256, PRE_SMEM_B>>>(g, W1);
    k_reduce<<<(N_SPANS * HPAD / 4 + 255) / 256, 256>>>();
    k_pairs<<<NPAIRS / 128, 256, KP_SMEM_B>>>(s_m, mids, aids, dist, genr, spk,
                                              W3, b2, b3, out);
}

// round 8
// speedup vs baseline: 3.0232x; 1.1924x over previous
#include <cuda_runtime.h>
#include <cuda_bf16.h>

// ---------------- problem constants ----------------
#define N_SPANS   2000
#define D_SPAN    1220
#define NPAIRS    65536
#define HID       150
#define HPAD      160          // padded hidden dim (zero-padded 150..159)
#define NPHI      189          // 9 bins * 7 genres * 3 speakers
#define NSLOTS    12           // 4 TA + 4 TB(lin) + 4 TB(sq) k-slots
#define KDIM      152          // padded layer-2 K (19 * 8)
#define NGRAN     38           // KDIM/4 granules per table row

// ---------------- scratch (static device memory; no allocs) ----------------
__device__ __align__(256) float    d_Cpart[NSLOTS][N_SPANS * HPAD];
__device__ __align__(256) float    d_TA[N_SPANS * HPAD];     // g[m] @ W1a
__device__ __align__(256) float    d_TB[N_SPANS * HPAD];     // g[a]@W1b + g[a]^2@W1c
__device__ __align__(256) float    d_TPHI[NPHI * HPAD];      // phi @ W1d + b1
__device__ __align__(256) unsigned d_W2t[KDIM * HPAD];       // W2 as tf32 bits, padded

__device__ __forceinline__ unsigned f2tf32(float x) {
    unsigned r;
    asm("cvt.rna.tf32.f32 %0, %1;" : "=r"(r) : "f"(x));
    return r;
}

__device__ __forceinline__ void mma_tf32(float& c0, float& c1, float& c2, float& c3,
                                         unsigned a0, unsigned a1, unsigned a2, unsigned a3,
                                         unsigned b0, unsigned b1)
{
    asm volatile(
        "mma.sync.aligned.m16n8k8.row.col.f32.tf32.tf32.f32 "
        "{%0,%1,%2,%3}, {%4,%5,%6,%7}, {%8,%9}, {%0,%1,%2,%3};\n"
        : "+f"(c0), "+f"(c1), "+f"(c2), "+f"(c3)
        : "r"(a0), "r"(a1), "r"(a2), "r"(a3), "r"(b0), "r"(b1));
}

__device__ __forceinline__ void cpa16(unsigned dst, const void* src, int srcsize) {
    asm volatile("cp.async.ca.shared.global [%0], [%1], 16, %2;\n"
                 :: "r"(dst), "l"(src), "r"(srcsize));
}
__device__ __forceinline__ void cpa8(unsigned dst, const void* src, int srcsize) {
    asm volatile("cp.async.ca.shared.global [%0], [%1], 8, %2;\n"
                 :: "r"(dst), "l"(src), "r"(srcsize));
}
__device__ __forceinline__ void cpa_commit() {
    asm volatile("cp.async.commit_group;\n");
}
__device__ __forceinline__ void cpa_wait0() {
    asm volatile("cp.async.wait_group 0;\n");
}

// =====================================================================
// K_prep: convert W2 (150x150) -> padded tf32 bits [152][160]
// =====================================================================
__global__ void k_prep(const float* __restrict__ W2)
{
    int idx = blockIdx.x * blockDim.x + threadIdx.x;
    if (idx < KDIM * HPAD) {
        int row = idx / HPAD;
        int j   = idx % HPAD;
        float v = (row < HID && j < HID) ? W2[row * HID + j] : 0.0f;
        d_W2t[idx] = f2tf32(v);
    }
}

// =====================================================================
// K_phi: TPHI[c][j] = b1[j] + phi-embedding combo c @ W1[3660..3719]
// =====================================================================
__global__ void k_phi(const float* __restrict__ de, const float* __restrict__ ge,
                      const float* __restrict__ se, const float* __restrict__ W1,
                      const float* __restrict__ b1)
{
    int c = blockIdx.x;
    int j = threadIdx.x;
    int bin = c / 21;
    int r   = c % 21;
    int gg  = r / 3;
    int ss  = r % 3;
    float v = 0.0f;
    if (j < HID) {
        v = b1[j];
        #pragma unroll
        for (int t = 0; t < 20; ++t) {
            v += de[bin * 20 + t] * W1[(3660 + t) * HID + j];
            v += ge[gg  * 20 + t] * W1[(3680 + t) * HID + j];
            v += se[ss  * 20 + t] * W1[(3700 + t) * HID + j];
        }
    }
    d_TPHI[c * HPAD + j] = v;
}

// =====================================================================
// K1: precompute TA / TB partials with TF32 mma, cp.async staging,
//     single-sync double-buffered chunk pipeline.
//   grid = (16 mtiles, 12 slots), 256 threads, BM=128, BN=160.
// =====================================================================
#define PRE_ATF_W   (2 * 128 * 36)     // 9216 words
#define PRE_BTF_W   (2 * 32 * 168)     // 10752 words
#define PRE_SMEM_W  (PRE_ATF_W + PRE_BTF_W)
#define PRE_SMEM_B  (PRE_SMEM_W * 4)

__global__ __launch_bounds__(256, 2) void k_precompute(const float* __restrict__ g,
                                                       const float* __restrict__ W1)
{
    extern __shared__ unsigned SP[];
    unsigned* Atf = SP;                 // 2 buffers of [128][36]
    unsigned* Btf = SP + PRE_ATF_W;     // 2 buffers of [32][168]

    const int mtile = blockIdx.x;          // 0..15
    const int slot  = blockIdx.y;          // 0..11
    const int mbase = mtile * 128;
    const int sub   = slot & 3;
    const int kbase = sub * 308;
    const int klen  = (sub == 3) ? 296 : 308;   // multiple of 4
    const int wrow0 = (slot < 4) ? 0 : ((slot < 8) ? 1220 : 2440);
    const bool sq   = (slot >= 8);

    const int tid  = threadIdx.x;
    const int lane = tid & 31;
    const int wid  = tid >> 5;
    const int mwarp = (wid & 1) * 64;
    const int jwarp = (wid >> 1) * 40;
    const int lq = lane >> 2;
    const int lr = lane & 3;

    const int am = tid >> 3;            // A: row group base (m = am + 32*it)
    const int aq = tid & 7;             // A: 16B quad within row
    const int brow = tid >> 3;          // B: k-row 0..31
    const int bj   = tid & 7;           // B: j2 = bj + 8*s

    unsigned a_smem_base = (unsigned)__cvta_generic_to_shared(Atf);
    unsigned b_smem_base = (unsigned)__cvta_generic_to_shared(Btf);

    float c[4][5][4];
    #pragma unroll
    for (int pt = 0; pt < 4; ++pt)
        #pragma unroll
        for (int nt = 0; nt < 5; ++nt)
            #pragma unroll
            for (int i = 0; i < 4; ++i) c[pt][nt][i] = 0.0f;

    auto stageA = [&](int ch, int bsel) {
        unsigned abase = a_smem_base + bsel * (128 * 36 * 4);
        if (!sq) {
            #pragma unroll
            for (int it = 0; it < 4; ++it) {
                int m  = am + it * 32;
                int kk = ch * 32 + aq * 4;
                int ok = ((mbase + m) < N_SPANS && kk < klen) ? 16 : 0;
                const float* src = g + (size_t)(mbase + (ok ? m : 0)) * D_SPAN
                                     + (ok ? (kbase + kk) : 0);
                cpa16(abase + (m * 36 + aq * 4) * 4, src, ok);
            }
        } else {
            unsigned* ab = (unsigned*)Atf + bsel * (128 * 36);
            #pragma unroll
            for (int it = 0; it < 4; ++it) {
                int m  = am + it * 32;
                int kk = ch * 32 + aq * 4;
                float4 v = make_float4(0.f, 0.f, 0.f, 0.f);
                if ((mbase + m) < N_SPANS && kk < klen)
                    v = *(const float4*)(g + (size_t)(mbase + m) * D_SPAN + kbase + kk);
                uint4 o;
                o.x = f2tf32(v.x * v.x);
                o.y = f2tf32(v.y * v.y);
                o.z = f2tf32(v.z * v.z);
                o.w = f2tf32(v.w * v.w);
                *(uint4*)(ab + m * 36 + aq * 4) = o;
            }
        }
    };
    auto stageB = [&](int ch, int bsel) {
        unsigned bbase = b_smem_base + bsel * (32 * 168 * 4);
        int kk = ch * 32 + brow;
        const float* rowp = W1 + (size_t)(wrow0 + kbase + ((kk < klen) ? kk : 0)) * HID;
        #pragma unroll
        for (int s = 0; s < 10; ++s) {
            int j2 = bj + 8 * s;        // 0..79
            int ok = (kk < klen && j2 < 75) ? 8 : 0;
            cpa8(bbase + (brow * 168 + j2 * 2) * 4, rowp + (ok ? j2 * 2 : 0), ok);
        }
    };

    stageA(0, 0);
    stageB(0, 0);
    cpa_commit();

    for (int ch = 0; ch < 10; ++ch) {
        const int buf = ch & 1;
        cpa_wait0();
        __syncthreads();
        if (ch < 9) {
            stageA(ch + 1, buf ^ 1);
            stageB(ch + 1, buf ^ 1);
            cpa_commit();
        }
        const unsigned* Ab = (const unsigned*)Atf + buf * (128 * 36);
        const unsigned* Bb = (const unsigned*)Btf + buf * (32 * 168);
        #pragma unroll
        for (int ks = 0; ks < 4; ++ks) {
            const int kcs = ks * 8;
            unsigned bfr[5][2];
            #pragma unroll
            for (int nt = 0; nt < 5; ++nt) {
                int j = jwarp + nt * 8 + lq;
                bfr[nt][0] = Bb[(kcs + lr)     * 168 + j];
                bfr[nt][1] = Bb[(kcs + lr + 4) * 168 + j];
            }
            #pragma unroll
            for (int pt = 0; pt < 4; ++pt) {
                int m = mwarp + pt * 16 + lq;
                unsigned a0 = Ab[m       * 36 + kcs + lr];
                unsigned a1 = Ab[(m + 8) * 36 + kcs + lr];
                unsigned a2 = Ab[m       * 36 + kcs + lr + 4];
                unsigned a3 = Ab[(m + 8) * 36 + kcs + lr + 4];
                #pragma unroll
                for (int nt = 0; nt < 5; ++nt)
                    mma_tf32(c[pt][nt][0], c[pt][nt][1], c[pt][nt][2], c[pt][nt][3],
                             a0, a1, a2, a3, bfr[nt][0], bfr[nt][1]);
            }
        }
    }

    float* dst = d_Cpart[slot];
    #pragma unroll
    for (int pt = 0; pt < 4; ++pt) {
        int m0 = mbase + mwarp + pt * 16 + lq;
        #pragma unroll
        for (int nt = 0; nt < 5; ++nt) {
            int j = jwarp + nt * 8 + 2 * lr;
            if (m0 < N_SPANS)
                *(float2*)(dst + (size_t)m0 * HPAD + j) = make_float2(c[pt][nt][0], c[pt][nt][1]);
            if (m0 + 8 < N_SPANS)
                *(float2*)(dst + (size_t)(m0 + 8) * HPAD + j) = make_float2(c[pt][nt][2], c[pt][nt][3]);
        }
    }
}

// =====================================================================
// K2: reduce k-split partials into TA / TB (float2, more blocks for
//     latency hiding at low per-thread MLP)
// =====================================================================
__global__ void k_reduce()
{
    int idx = blockIdx.x * blockDim.x + threadIdx.x;
    if (idx < N_SPANS * HPAD / 2) {
        float2 ta = make_float2(0.f, 0.f);
        float2 tb = ta;
        #pragma unroll
        for (int s = 0; s < 4; ++s) {
            float2 v = ((const float2*)d_Cpart[s])[idx];
            ta.x += v.x; ta.y += v.y;
        }
        #pragma unroll
        for (int s = 4; s < 12; ++s) {
            float2 v = ((const float2*)d_Cpart[s])[idx];
            tb.x += v.x; tb.y += v.y;
        }
        ((float2*)d_TA)[idx] = ta;
        ((float2*)d_TB)[idx] = tb;
    }
}

// =====================================================================
// K3: fused pair kernel, single-sync double-buffered chunk pipeline.
//   512 blocks x 256 threads; 128 pairs / block.
//   COALESCED gather: lane = (pair_group, kseg); 8 consecutive lanes read
//   one pair's 128B row segment -> 4 cache lines per warp LDG (was 32).
//   H1 chunk buffers [p][k] stride 36; W2 chunks [k][j] stride 168 (cp.async).
// =====================================================================
#define KP_HB_W   (2 * 128 * 36)       // 9216 words
#define KP_WB_W   (2 * 32 * 168)       // 10752 words
#define KP_OFF_W3 (KP_HB_W + KP_WB_W)  // 19968
#define KP_OFF_B2 (KP_OFF_W3 + HPAD)
#define KP_OFF_SB (KP_OFF_B2 + HPAD)
#define KP_OFF_M  (KP_OFF_SB + 128)
#define KP_OFF_A  (KP_OFF_M + 128)
#define KP_OFF_C  (KP_OFF_A + 128)
#define KP_SMEM_W (KP_OFF_C + 128)
#define KP_SMEM_B (KP_SMEM_W * 4)

__global__ __launch_bounds__(256, 2) void k_pairs(
    const float* __restrict__ s_m, const int* __restrict__ mids,
    const int* __restrict__ aids, const int* __restrict__ dist,
    const int* __restrict__ genre, const int* __restrict__ spk,
    const float* __restrict__ W3, const float* __restrict__ b2,
    const float* __restrict__ b3, float* __restrict__ out)
{
    extern __shared__ unsigned SU[];
    unsigned* Hb  = SU;                       // 2 x [128][36]
    unsigned* Wb  = SU + KP_HB_W;             // 2 x [32][168]
    float*    W3s = (float*)(SU + KP_OFF_W3);
    float*    b2s = (float*)(SU + KP_OFF_B2);
    float*    sbS = (float*)(SU + KP_OFF_SB);
    int*      mS  = (int*)(SU + KP_OFF_M);
    int*      aS  = (int*)(SU + KP_OFF_A);
    int*      cS  = (int*)(SU + KP_OFF_C);
    float*    red = (float*)(Wb + 32 * 168);  // alias buffer 1 of Wb

    const int tid   = threadIdx.x;
    const int lane  = tid & 31;
    const int wid   = tid >> 5;
    const int pbase = blockIdx.x * 128;

    // ---- per-pair metadata -> smem ----
    if (tid < 128) {
        int p = pbase + tid;
        int m = mids[p];
        int a = aids[p];
        mS[tid] = m;
        aS[tid] = a;
        int d = dist[p];
        int bin;
        if      (d >= 64) bin = 8;
        else if (d >= 32) bin = 7;
        else if (d >= 16) bin = 6;
        else if (d >= 8)  bin = 5;
        else if (d >= 5)  bin = 4;
        else              bin = (d >= 1) ? (d - 1) : 0;
        cS[tid] = (bin * 7 + genre[p]) * 3 + spk[p];
        sbS[tid] = s_m[m] + s_m[a];
    }
    if (tid < HPAD) {
        float w3v = 0.0f, b2v = 0.0f;
        if (tid < HID) { w3v = W3[tid]; b2v = b2[tid]; }
        W3s[tid] = w3v;
        b2s[tid] = b2v;
    }

    unsigned w_smem_base = (unsigned)__cvta_generic_to_shared(Wb);

    auto stageW2 = [&](int ch, int bsel) {
        unsigned wb = w_smem_base + bsel * (32 * 168 * 4);
        const int rows = (ch == 4) ? 24 : 32;
        for (int i4 = tid; i4 < rows * 40; i4 += 256) {
            int row = i4 / 40;
            int j4  = i4 - row * 40;
            cpa16(wb + (row * 168 + j4 * 4) * 4,
                  d_W2t + (ch * 32 + row) * HPAD + j4 * 4, 16);
        }
    };

    // ---- coalesced gather: thread = (pair_row, kseg) ----
    const int kseg = tid & 7;           // 16B granule within 32-k chunk
    const int pr   = tid >> 3;          // 0..31 pair row base
    auto gather = [&](int ch, int bsel) {
        unsigned* hb = Hb + bsel * (128 * 36);
        const int kk = ch * 8 + kseg;   // global granule 0..39
        if (kk < NGRAN) {
            #pragma unroll
            for (int it = 0; it < 4; ++it) {
                int p = pr + it * 32;
                int m = mS[p], a = aS[p], cc = cS[p];
                float4 va = ((const float4*)d_TA)  [m  * 40 + kk];
                float4 vb = ((const float4*)d_TB)  [a  * 40 + kk];
                float4 vc = ((const float4*)d_TPHI)[cc * 40 + kk];
                uint4 o;
                o.x = f2tf32(fmaxf(va.x + vb.x + vc.x, 0.0f));
                o.y = f2tf32(fmaxf(va.y + vb.y + vc.y, 0.0f));
                o.z = f2tf32(fmaxf(va.z + vb.z + vc.z, 0.0f));
                o.w = f2tf32(fmaxf(va.w + vb.w + vc.w, 0.0f));
                *(uint4*)(hb + p * 36 + kseg * 4) = o;
            }
        }
    };

    // ---- MMA tiling ----
    const int pwarp = (wid & 1) * 64;
    const int jwarp = (wid >> 1) * 40;
    const int lq = lane >> 2;
    const int lr = lane & 3;

    float c[4][5][4];
    #pragma unroll
    for (int pt = 0; pt < 4; ++pt)
        #pragma unroll
        for (int nt = 0; nt < 5; ++nt)
            #pragma unroll
            for (int i = 0; i < 4; ++i) c[pt][nt][i] = 0.0f;

    // ---- pipeline ----
    stageW2(0, 0);
    cpa_commit();
    __syncthreads();                    // metadata visible
    gather(0, 0);

    for (int ch = 0; ch < 5; ++ch) {
        const int buf = ch & 1;
        cpa_wait0();
        __syncthreads();                // H1[buf] + W2[buf] ready
        if (ch < 4) {
            stageW2(ch + 1, buf ^ 1);
            cpa_commit();
            gather(ch + 1, buf ^ 1);
        }
        const unsigned* hb = Hb + buf * (128 * 36);
        const unsigned* wb = Wb + buf * (32 * 168);
        const int nks = (ch == 4) ? 3 : 4;
        for (int ks = 0; ks < nks; ++ks) {
            const int kcs = ks * 8;
            unsigned bfr[5][2];
            #pragma unroll
            for (int nt = 0; nt < 5; ++nt) {
                int j = jwarp + nt * 8 + lq;
                bfr[nt][0] = wb[(kcs + lr)     * 168 + j];
                bfr[nt][1] = wb[(kcs + lr + 4) * 168 + j];
            }
            #pragma unroll
            for (int pt = 0; pt < 4; ++pt) {
                int pp = pwarp + pt * 16 + lq;
                unsigned a0 = hb[pp       * 36 + kcs + lr];
                unsigned a1 = hb[(pp + 8) * 36 + kcs + lr];
                unsigned a2 = hb[pp       * 36 + kcs + lr + 4];
                unsigned a3 = hb[(pp + 8) * 36 + kcs + lr + 4];
                #pragma unroll
                for (int nt = 0; nt < 5; ++nt)
                    mma_tf32(c[pt][nt][0], c[pt][nt][1], c[pt][nt][2], c[pt][nt][3],
                             a0, a1, a2, a3, bfr[nt][0], bfr[nt][1]);
            }
        }
    }

    // ---- epilogue: relu(+b2) dot W3 ----
    float sp[4][2];
    #pragma unroll
    for (int pt = 0; pt < 4; ++pt) { sp[pt][0] = 0.0f; sp[pt][1] = 0.0f; }

    #pragma unroll
    for (int nt = 0; nt < 5; ++nt) {
        int j = jwarp + nt * 8 + 2 * lr;
        float w3a = W3s[j],     b2a = b2s[j];
        float w3b = W3s[j + 1], b2b = b2s[j + 1];
        #pragma unroll
        for (int pt = 0; pt < 4; ++pt) {
            sp[pt][0] += fmaxf(c[pt][nt][0] + b2a, 0.0f) * w3a;
            sp[pt][0] += fmaxf(c[pt][nt][1] + b2b, 0.0f) * w3b;
            sp[pt][1] += fmaxf(c[pt][nt][2] + b2a, 0.0f) * w3a;
            sp[pt][1] += fmaxf(c[pt][nt][3] + b2b, 0.0f) * w3b;
        }
    }
    #pragma unroll
    for (int pt = 0; pt < 4; ++pt) {
        #pragma unroll
        for (int h = 0; h < 2; ++h) {
            sp[pt][h] += __shfl_xor_sync(0xffffffffu, sp[pt][h], 1);
            sp[pt][h] += __shfl_xor_sync(0xffffffffu, sp[pt][h], 2);
        }
    }

    // red aliases Wb buffer 1 (last MMA chunk used buffer 0)
    const int jg = wid >> 1;
    if (lr == 0) {
        #pragma unroll
        for (int pt = 0; pt < 4; ++pt) {
            int pp = pwarp + pt * 16 + lq;
            red[jg * 128 + pp]     = sp[pt][0];
            red[jg * 128 + pp + 8] = sp[pt][1];
        }
    }
    __syncthreads();

    if (tid < 128) {
        float t = red[tid] + red[128 + tid] + red[256 + tid] + red[384 + tid];
        out[pbase + tid] = t + b3[0] + sbS[tid];
    }
}

// =====================================================================
// launch
// =====================================================================
extern "C" void kernel_launch(void* const* d_in, const int* in_sizes, int n_in,
                              void* d_out, int out_size)
{
    const float* g    = (const float*)d_in[0];
    const float* s_m  = (const float*)d_in[1];
    const int*   mids = (const int*)d_in[2];
    const int*   aids = (const int*)d_in[3];
    const int*   dist = (const int*)d_in[4];
    const int*   genr = (const int*)d_in[5];
    const int*   spk  = (const int*)d_in[6];
    const float* de   = (const float*)d_in[7];
    const float* ge   = (const float*)d_in[8];
    const float* se   = (const float*)d_in[9];
    const float* W1   = (const float*)d_in[10];
    const float* b1   = (const float*)d_in[11];
    const float* W2   = (const float*)d_in[12];
    const float* b2   = (const float*)d_in[13];
    const float* W3   = (const float*)d_in[14];
    const float* b3   = (const float*)d_in[15];
    float* out = (float*)d_out;

    static int attr_done = 0;
    if (!attr_done) {
        cudaFuncSetAttribute(k_precompute, cudaFuncAttributeMaxDynamicSharedMemorySize, PRE_SMEM_B);
        cudaFuncSetAttribute(k_pairs, cudaFuncAttributeMaxDynamicSharedMemorySize, KP_SMEM_B);
        attr_done = 1;
    }

    k_prep<<<(KDIM * HPAD + 255) / 256, 256>>>(W2);
    k_phi<<<NPHI, HPAD>>>(de, ge, se, W1, b1);
    k_precompute<<<dim3(16, NSLOTS), 256, PRE_SMEM_B>>>(g, W1);
    k_reduce<<<(N_SPANS * HPAD / 2 + 255) / 256, 256>>>();
    k_pairs<<<NPAIRS / 128, 256, KP_SMEM_B>>>(s_m, mids, aids, dist, genr, spk,
                                              W3, b2, b3, out);
}

// round 9
// speedup vs baseline: 3.7252x; 1.2322x over previous
#include <cuda_runtime.h>
#include <cuda_bf16.h>

// ---------------- problem constants ----------------
#define N_SPANS   2000
#define D_SPAN    1220
#define NPAIRS    65536
#define HID       150
#define HPAD      160          // padded hidden dim (zero-padded 150..159)
#define NPHI      189          // 9 bins * 7 genres * 3 speakers
#define NSLOTS    18           // 6 TA + 6 TB(lin) + 6 TB(sq) k-slots
#define KDIM      152          // padded layer-2 K (19 * 8)
#define NGRAN     38           // KDIM/4 granules per table row

// ---------------- scratch (static device memory; no allocs) ----------------
__device__ __align__(256) float    d_Cpart[NSLOTS][N_SPANS * HPAD];
__device__ __align__(256) float    d_TA[N_SPANS * HPAD];     // g[m] @ W1a
__device__ __align__(256) float    d_TB[N_SPANS * HPAD];     // g[a]@W1b + g[a]^2@W1c
__device__ __align__(256) float    d_TPHI[NPHI * HPAD];      // phi @ W1d + b1
__device__ __align__(256) unsigned d_W2t[KDIM * HPAD];       // W2 as tf32 bits, padded

__device__ __forceinline__ unsigned f2tf32(float x) {
    unsigned r;
    asm("cvt.rna.tf32.f32 %0, %1;" : "=r"(r) : "f"(x));
    return r;
}

__device__ __forceinline__ void mma_tf32(float& c0, float& c1, float& c2, float& c3,
                                         unsigned a0, unsigned a1, unsigned a2, unsigned a3,
                                         unsigned b0, unsigned b1)
{
    asm volatile(
        "mma.sync.aligned.m16n8k8.row.col.f32.tf32.tf32.f32 "
        "{%0,%1,%2,%3}, {%4,%5,%6,%7}, {%8,%9}, {%0,%1,%2,%3};\n"
        : "+f"(c0), "+f"(c1), "+f"(c2), "+f"(c3)
        : "r"(a0), "r"(a1), "r"(a2), "r"(a3), "r"(b0), "r"(b1));
}

__device__ __forceinline__ void cpa16(unsigned dst, const void* src, int srcsize) {
    asm volatile("cp.async.ca.shared.global [%0], [%1], 16, %2;\n"
                 :: "r"(dst), "l"(src), "r"(srcsize));
}
__device__ __forceinline__ void cpa8(unsigned dst, const void* src, int srcsize) {
    asm volatile("cp.async.ca.shared.global [%0], [%1], 8, %2;\n"
                 :: "r"(dst), "l"(src), "r"(srcsize));
}
__device__ __forceinline__ void cpa_commit() {
    asm volatile("cp.async.commit_group;\n");
}
__device__ __forceinline__ void cpa_wait0() {
    asm volatile("cp.async.wait_group 0;\n");
}

// =====================================================================
// K_prepphi: fused W2->tf32 conversion (blocks 0..94) and TPHI build
// (blocks 95..283).  Keeps k_pairs as the 4th launch for ncu capture.
// =====================================================================
#define PREP_BLOCKS 95         // 95*256 = 24320 = KDIM*HPAD exactly

__global__ void k_prepphi(const float* __restrict__ W2,
                          const float* __restrict__ de, const float* __restrict__ ge,
                          const float* __restrict__ se, const float* __restrict__ W1,
                          const float* __restrict__ b1)
{
    if (blockIdx.x < PREP_BLOCKS) {
        int idx = blockIdx.x * 256 + threadIdx.x;     // < KDIM*HPAD
        int row = idx / HPAD;
        int j   = idx % HPAD;
        float v = (row < HID && j < HID) ? W2[row * HID + j] : 0.0f;
        d_W2t[idx] = f2tf32(v);
    } else {
        int c = blockIdx.x - PREP_BLOCKS;             // 0..NPHI-1
        int j = threadIdx.x;
        if (j < HPAD) {
            int bin = c / 21;
            int r   = c % 21;
            int gg  = r / 3;
            int ss  = r % 3;
            float v = 0.0f;
            if (j < HID) {
                v = b1[j];
                #pragma unroll
                for (int t = 0; t < 20; ++t) {
                    v += de[bin * 20 + t] * W1[(3660 + t) * HID + j];
                    v += ge[gg  * 20 + t] * W1[(3680 + t) * HID + j];
                    v += se[ss  * 20 + t] * W1[(3700 + t) * HID + j];
                }
            }
            d_TPHI[c * HPAD + j] = v;
        }
    }
}

// =====================================================================
// K1: precompute TA / TB partials with TF32 mma, cp.async staging,
//     single-sync double-buffered chunk pipeline.
//   grid = (16 mtiles, 18 slots) = 288 blocks -> one clean wave at
//   2 blocks/SM (capacity 296); busiest-SM makespan 2x7 chunk-units.
//   slot type = slot/6: 0=TA (W1 rows 0..), 1=TBlin (+1220), 2=TBsq (+2440, A=g^2)
//   sub = slot%6: kbase = sub*204, klen = {204,...,204,200}; 7 chunks of 32.
// =====================================================================
#define PRE_ATF_W   (2 * 128 * 36)     // 9216 words
#define PRE_BTF_W   (2 * 32 * 168)     // 10752 words
#define PRE_SMEM_W  (PRE_ATF_W + PRE_BTF_W)
#define PRE_SMEM_B  (PRE_SMEM_W * 4)

__global__ __launch_bounds__(256, 2) void k_precompute(const float* __restrict__ g,
                                                       const float* __restrict__ W1)
{
    extern __shared__ unsigned SP[];
    unsigned* Atf = SP;                 // 2 buffers of [128][36]
    unsigned* Btf = SP + PRE_ATF_W;     // 2 buffers of [32][168]

    const int mtile = blockIdx.x;          // 0..15
    const int slot  = blockIdx.y;          // 0..17
    const int mbase = mtile * 128;
    const int type  = slot / 6;            // 0 TA, 1 TBlin, 2 TBsq
    const int sub   = slot % 6;
    const int kbase = sub * 204;
    const int klen  = (sub == 5) ? 200 : 204;
    const int wrow0 = type * 1220;
    const bool sq   = (type == 2);

    const int tid  = threadIdx.x;
    const int lane = tid & 31;
    const int wid  = tid >> 5;
    const int mwarp = (wid & 1) * 64;
    const int jwarp = (wid >> 1) * 40;
    const int lq = lane >> 2;
    const int lr = lane & 3;

    const int am = tid >> 3;            // A: row group base (m = am + 32*it)
    const int aq = tid & 7;             // A: 16B quad within row
    const int brow = tid >> 3;          // B: k-row 0..31
    const int bj   = tid & 7;           // B: j2 = bj + 8*s

    unsigned a_smem_base = (unsigned)__cvta_generic_to_shared(Atf);
    unsigned b_smem_base = (unsigned)__cvta_generic_to_shared(Btf);

    float c[4][5][4];
    #pragma unroll
    for (int pt = 0; pt < 4; ++pt)
        #pragma unroll
        for (int nt = 0; nt < 5; ++nt)
            #pragma unroll
            for (int i = 0; i < 4; ++i) c[pt][nt][i] = 0.0f;

    auto stageA = [&](int ch, int bsel) {
        unsigned abase = a_smem_base + bsel * (128 * 36 * 4);
        if (!sq) {
            #pragma unroll
            for (int it = 0; it < 4; ++it) {
                int m  = am + it * 32;
                int kk = ch * 32 + aq * 4;
                int ok = ((mbase + m) < N_SPANS && kk < klen) ? 16 : 0;
                const float* src = g + (size_t)(mbase + (ok ? m : 0)) * D_SPAN
                                     + (ok ? (kbase + kk) : 0);
                cpa16(abase + (m * 36 + aq * 4) * 4, src, ok);
            }
        } else {
            unsigned* ab = (unsigned*)Atf + bsel * (128 * 36);
            #pragma unroll
            for (int it = 0; it < 4; ++it) {
                int m  = am + it * 32;
                int kk = ch * 32 + aq * 4;
                float4 v = make_float4(0.f, 0.f, 0.f, 0.f);
                if ((mbase + m) < N_SPANS && kk < klen)
                    v = *(const float4*)(g + (size_t)(mbase + m) * D_SPAN + kbase + kk);
                uint4 o;
                o.x = f2tf32(v.x * v.x);
                o.y = f2tf32(v.y * v.y);
                o.z = f2tf32(v.z * v.z);
                o.w = f2tf32(v.w * v.w);
                *(uint4*)(ab + m * 36 + aq * 4) = o;
            }
        }
    };
    auto stageB = [&](int ch, int bsel) {
        unsigned bbase = b_smem_base + bsel * (32 * 168 * 4);
        int kk = ch * 32 + brow;
        const float* rowp = W1 + (size_t)(wrow0 + kbase + ((kk < klen) ? kk : 0)) * HID;
        #pragma unroll
        for (int s = 0; s < 10; ++s) {
            int j2 = bj + 8 * s;        // 0..79
            int ok = (kk < klen && j2 < 75) ? 8 : 0;
            cpa8(bbase + (brow * 168 + j2 * 2) * 4, rowp + (ok ? j2 * 2 : 0), ok);
        }
    };

    stageA(0, 0);
    stageB(0, 0);
    cpa_commit();

    for (int ch = 0; ch < 7; ++ch) {            // 7 chunks cover klen <= 224
        const int buf = ch & 1;
        cpa_wait0();
        __syncthreads();
        if (ch < 6) {
            stageA(ch + 1, buf ^ 1);
            stageB(ch + 1, buf ^ 1);
            cpa_commit();
        }
        const unsigned* Ab = (const unsigned*)Atf + buf * (128 * 36);
        const unsigned* Bb = (const unsigned*)Btf + buf * (32 * 168);
        #pragma unroll
        for (int ks = 0; ks < 4; ++ks) {
            const int kcs = ks * 8;
            unsigned bfr[5][2];
            #pragma unroll
            for (int nt = 0; nt < 5; ++nt) {
                int j = jwarp + nt * 8 + lq;
                bfr[nt][0] = Bb[(kcs + lr)     * 168 + j];
                bfr[nt][1] = Bb[(kcs + lr + 4) * 168 + j];
            }
            #pragma unroll
            for (int pt = 0; pt < 4; ++pt) {
                int m = mwarp + pt * 16 + lq;
                unsigned a0 = Ab[m       * 36 + kcs + lr];
                unsigned a1 = Ab[(m + 8) * 36 + kcs + lr];
                unsigned a2 = Ab[m       * 36 + kcs + lr + 4];
                unsigned a3 = Ab[(m + 8) * 36 + kcs + lr + 4];
                #pragma unroll
                for (int nt = 0; nt < 5; ++nt)
                    mma_tf32(c[pt][nt][0], c[pt][nt][1], c[pt][nt][2], c[pt][nt][3],
                             a0, a1, a2, a3, bfr[nt][0], bfr[nt][1]);
            }
        }
    }

    float* dst = d_Cpart[slot];
    #pragma unroll
    for (int pt = 0; pt < 4; ++pt) {
        int m0 = mbase + mwarp + pt * 16 + lq;
        #pragma unroll
        for (int nt = 0; nt < 5; ++nt) {
            int j = jwarp + nt * 8 + 2 * lr;
            if (m0 < N_SPANS)
                *(float2*)(dst + (size_t)m0 * HPAD + j) = make_float2(c[pt][nt][0], c[pt][nt][1]);
            if (m0 + 8 < N_SPANS)
                *(float2*)(dst + (size_t)(m0 + 8) * HPAD + j) = make_float2(c[pt][nt][2], c[pt][nt][3]);
        }
    }
}

// =====================================================================
// K2: reduce k-split partials into TA / TB (float2)
// =====================================================================
__global__ void k_reduce()
{
    int idx = blockIdx.x * blockDim.x + threadIdx.x;
    if (idx < N_SPANS * HPAD / 2) {
        float2 ta = make_float2(0.f, 0.f);
        float2 tb = ta;
        #pragma unroll
        for (int s = 0; s < 6; ++s) {
            float2 v = ((const float2*)d_Cpart[s])[idx];
            ta.x += v.x; ta.y += v.y;
        }
        #pragma unroll
        for (int s = 6; s < 18; ++s) {
            float2 v = ((const float2*)d_Cpart[s])[idx];
            tb.x += v.x; tb.y += v.y;
        }
        ((float2*)d_TA)[idx] = ta;
        ((float2*)d_TB)[idx] = tb;
    }
}

// =====================================================================
// K3: fused pair kernel, single-sync double-buffered chunk pipeline.
//   512 blocks x 256 threads; 128 pairs / block.  (4th launch -> ncu.)
// =====================================================================
#define KP_HB_W   (2 * 128 * 36)       // 9216 words
#define KP_WB_W   (2 * 32 * 168)       // 10752 words
#define KP_OFF_W3 (KP_HB_W + KP_WB_W)  // 19968
#define KP_OFF_B2 (KP_OFF_W3 + HPAD)
#define KP_OFF_SB (KP_OFF_B2 + HPAD)
#define KP_OFF_M  (KP_OFF_SB + 128)
#define KP_OFF_A  (KP_OFF_M + 128)
#define KP_OFF_C  (KP_OFF_A + 128)
#define KP_SMEM_W (KP_OFF_C + 128)
#define KP_SMEM_B (KP_SMEM_W * 4)

__global__ __launch_bounds__(256, 2) void k_pairs(
    const float* __restrict__ s_m, const int* __restrict__ mids,
    const int* __restrict__ aids, const int* __restrict__ dist,
    const int* __restrict__ genre, const int* __restrict__ spk,
    const float* __restrict__ W3, const float* __restrict__ b2,
    const float* __restrict__ b3, float* __restrict__ out)
{
    extern __shared__ unsigned SU[];
    unsigned* Hb  = SU;                       // 2 x [128][36]
    unsigned* Wb  = SU + KP_HB_W;             // 2 x [32][168]
    float*    W3s = (float*)(SU + KP_OFF_W3);
    float*    b2s = (float*)(SU + KP_OFF_B2);
    float*    sbS = (float*)(SU + KP_OFF_SB);
    int*      mS  = (int*)(SU + KP_OFF_M);
    int*      aS  = (int*)(SU + KP_OFF_A);
    int*      cS  = (int*)(SU + KP_OFF_C);
    float*    red = (float*)(Wb + 32 * 168);  // alias buffer 1 of Wb

    const int tid   = threadIdx.x;
    const int lane  = tid & 31;
    const int wid   = tid >> 5;
    const int pbase = blockIdx.x * 128;

    // ---- per-pair metadata -> smem ----
    if (tid < 128) {
        int p = pbase + tid;
        int m = mids[p];
        int a = aids[p];
        mS[tid] = m;
        aS[tid] = a;
        int d = dist[p];
        int bin;
        if      (d >= 64) bin = 8;
        else if (d >= 32) bin = 7;
        else if (d >= 16) bin = 6;
        else if (d >= 8)  bin = 5;
        else if (d >= 5)  bin = 4;
        else              bin = (d >= 1) ? (d - 1) : 0;
        cS[tid] = (bin * 7 + genre[p]) * 3 + spk[p];
        sbS[tid] = s_m[m] + s_m[a];
    }
    if (tid < HPAD) {
        float w3v = 0.0f, b2v = 0.0f;
        if (tid < HID) { w3v = W3[tid]; b2v = b2[tid]; }
        W3s[tid] = w3v;
        b2s[tid] = b2v;
    }

    unsigned w_smem_base = (unsigned)__cvta_generic_to_shared(Wb);

    auto stageW2 = [&](int ch, int bsel) {
        unsigned wb = w_smem_base + bsel * (32 * 168 * 4);
        const int rows = (ch == 4) ? 24 : 32;
        for (int i4 = tid; i4 < rows * 40; i4 += 256) {
            int row = i4 / 40;
            int j4  = i4 - row * 40;
            cpa16(wb + (row * 168 + j4 * 4) * 4,
                  d_W2t + (ch * 32 + row) * HPAD + j4 * 4, 16);
        }
    };

    // ---- coalesced gather: thread = (pair_row, kseg) ----
    const int kseg = tid & 7;           // 16B granule within 32-k chunk
    const int pr   = tid >> 3;          // 0..31 pair row base
    auto gather = [&](int ch, int bsel) {
        unsigned* hb = Hb + bsel * (128 * 36);
        const int kk = ch * 8 + kseg;   // global granule 0..39
        if (kk < NGRAN) {
            #pragma unroll
            for (int it = 0; it < 4; ++it) {
                int p = pr + it * 32;
                int m = mS[p], a = aS[p], cc = cS[p];
                float4 va = ((const float4*)d_TA)  [m  * 40 + kk];
                float4 vb = ((const float4*)d_TB)  [a  * 40 + kk];
                float4 vc = ((const float4*)d_TPHI)[cc * 40 + kk];
                uint4 o;
                o.x = f2tf32(fmaxf(va.x + vb.x + vc.x, 0.0f));
                o.y = f2tf32(fmaxf(va.y + vb.y + vc.y, 0.0f));
                o.z = f2tf32(fmaxf(va.z + vb.z + vc.z, 0.0f));
                o.w = f2tf32(fmaxf(va.w + vb.w + vc.w, 0.0f));
                *(uint4*)(hb + p * 36 + kseg * 4) = o;
            }
        }
    };

    // ---- MMA tiling ----
    const int pwarp = (wid & 1) * 64;
    const int jwarp = (wid >> 1) * 40;
    const int lq = lane >> 2;
    const int lr = lane & 3;

    float c[4][5][4];
    #pragma unroll
    for (int pt = 0; pt < 4; ++pt)
        #pragma unroll
        for (int nt = 0; nt < 5; ++nt)
            #pragma unroll
            for (int i = 0; i < 4; ++i) c[pt][nt][i] = 0.0f;

    // ---- pipeline ----
    stageW2(0, 0);
    cpa_commit();
    __syncthreads();                    // metadata visible
    gather(0, 0);

    for (int ch = 0; ch < 5; ++ch) {
        const int buf = ch & 1;
        cpa_wait0();
        __syncthreads();                // H1[buf] + W2[buf] ready
        if (ch < 4) {
            stageW2(ch + 1, buf ^ 1);
            cpa_commit();
            gather(ch + 1, buf ^ 1);
        }
        const unsigned* hb = Hb + buf * (128 * 36);
        const unsigned* wb = Wb + buf * (32 * 168);
        const int nks = (ch == 4) ? 3 : 4;
        for (int ks = 0; ks < nks; ++ks) {
            const int kcs = ks * 8;
            unsigned bfr[5][2];
            #pragma unroll
            for (int nt = 0; nt < 5; ++nt) {
                int j = jwarp + nt * 8 + lq;
                bfr[nt][0] = wb[(kcs + lr)     * 168 + j];
                bfr[nt][1] = wb[(kcs + lr + 4) * 168 + j];
            }
            #pragma unroll
            for (int pt = 0; pt < 4; ++pt) {
                int pp = pwarp + pt * 16 + lq;
                unsigned a0 = hb[pp       * 36 + kcs + lr];
                unsigned a1 = hb[(pp + 8) * 36 + kcs + lr];
                unsigned a2 = hb[pp       * 36 + kcs + lr + 4];
                unsigned a3 = hb[(pp + 8) * 36 + kcs + lr + 4];
                #pragma unroll
                for (int nt = 0; nt < 5; ++nt)
                    mma_tf32(c[pt][nt][0], c[pt][nt][1], c[pt][nt][2], c[pt][nt][3],
                             a0, a1, a2, a3, bfr[nt][0], bfr[nt][1]);
            }
        }
    }

    // ---- epilogue: relu(+b2) dot W3 ----
    float sp[4][2];
    #pragma unroll
    for (int pt = 0; pt < 4; ++pt) { sp[pt][0] = 0.0f; sp[pt][1] = 0.0f; }

    #pragma unroll
    for (int nt = 0; nt < 5; ++nt) {
        int j = jwarp + nt * 8 + 2 * lr;
        float w3a = W3s[j],     b2a = b2s[j];
        float w3b = W3s[j + 1], b2b = b2s[j + 1];
        #pragma unroll
        for (int pt = 0; pt < 4; ++pt) {
            sp[pt][0] += fmaxf(c[pt][nt][0] + b2a, 0.0f) * w3a;
            sp[pt][0] += fmaxf(c[pt][nt][1] + b2b, 0.0f) * w3b;
            sp[pt][1] += fmaxf(c[pt][nt][2] + b2a, 0.0f) * w3a;
            sp[pt][1] += fmaxf(c[pt][nt][3] + b2b, 0.0f) * w3b;
        }
    }
    #pragma unroll
    for (int pt = 0; pt < 4; ++pt) {
        #pragma unroll
        for (int h = 0; h < 2; ++h) {
            sp[pt][h] += __shfl_xor_sync(0xffffffffu, sp[pt][h], 1);
            sp[pt][h] += __shfl_xor_sync(0xffffffffu, sp[pt][h], 2);
        }
    }

    // red aliases Wb buffer 1 (last MMA chunk used buffer 0)
    const int jg = wid >> 1;
    if (lr == 0) {
        #pragma unroll
        for (int pt = 0; pt < 4; ++pt) {
            int pp = pwarp + pt * 16 + lq;
            red[jg * 128 + pp]     = sp[pt][0];
            red[jg * 128 + pp + 8] = sp[pt][1];
        }
    }
    __syncthreads();

    if (tid < 128) {
        float t = red[tid] + red[128 + tid] + red[256 + tid] + red[384 + tid];
        out[pbase + tid] = t + b3[0] + sbS[tid];
    }
}

// =====================================================================
// launch
// =====================================================================
extern "C" void kernel_launch(void* const* d_in, const int* in_sizes, int n_in,
                              void* d_out, int out_size)
{
    const float* g    = (const float*)d_in[0];
    const float* s_m  = (const float*)d_in[1];
    const int*   mids = (const int*)d_in[2];
    const int*   aids = (const int*)d_in[3];
    const int*   dist = (const int*)d_in[4];
    const int*   genr = (const int*)d_in[5];
    const int*   spk  = (const int*)d_in[6];
    const float* de   = (const float*)d_in[7];
    const float* ge   = (const float*)d_in[8];
    const float* se   = (const float*)d_in[9];
    const float* W1   = (const float*)d_in[10];
    const float* b1   = (const float*)d_in[11];
    const float* W2   = (const float*)d_in[12];
    const float* b2   = (const float*)d_in[13];
    const float* W3   = (const float*)d_in[14];
    const float* b3   = (const float*)d_in[15];
    float* out = (float*)d_out;

    static int attr_done = 0;
    if (!attr_done) {
        cudaFuncSetAttribute(k_precompute, cudaFuncAttributeMaxDynamicSharedMemorySize, PRE_SMEM_B);
        cudaFuncSetAttribute(k_pairs, cudaFuncAttributeMaxDynamicSharedMemorySize, KP_SMEM_B);
        attr_done = 1;
    }

    k_prepphi<<<PREP_BLOCKS + NPHI, 256>>>(W2, de, ge, se, W1, b1);
    k_precompute<<<dim3(16, NSLOTS), 256, PRE_SMEM_B>>>(g, W1);
    k_reduce<<<(N_SPANS * HPAD / 2 + 255) / 256, 256>>>();
    k_pairs<<<NPAIRS / 128, 256, KP_SMEM_B>>>(s_m, mids, aids, dist, genr, spk,
                                              W3, b2, b3, out);
}